// round 1
// baseline (speedup 1.0000x reference)
#include <cuda_runtime.h>

// Problem constants
#define SEQ   2048
#define BATCH 2
#define DM    1024
#define NH    16
#define DH    64
#define MTOK  (SEQ*BATCH)   // 4096 token rows

// ---------------- scratch (device globals: allocation-free rule) ----------
__device__ float g_q  [MTOK * DM];        // 16 MB
__device__ float g_kv [MTOK * 2 * DM];    // 32 MB
__device__ float g_vec[MTOK * DM];        // 16 MB
__device__ float g_h0 [MTOK * DM];        // dec + attn_out
__device__ float g_h1 [MTOK * DM];        // LN1 out
__device__ float g_f0 [MTOK * DM];        // h1 + ff

// ================= GEMM: C[M,N] = A[M,K] * B[N,K]^T (+ optional Add) ======
// A row-major [M,K], B row-major [N,K] (K contiguous for both: "NT" form).
// 128x128x16 tile, 256 threads, 8x8 per-thread microtile.
template<bool ADD>
__global__ void __launch_bounds__(256) gemm_nt(
    const float* __restrict__ A, const float* __restrict__ B,
    const float* __restrict__ Add, float* __restrict__ C,
    int M, int N, int K)
{
    __shared__ float At[16][132];
    __shared__ float Bt[16][132];
    const int tid = threadIdx.x;
    const int tx = tid & 15, ty = tid >> 4;
    const int bm = blockIdx.y * 128, bn = blockIdx.x * 128;

    float acc[8][8] = {};

    for (int k0 = 0; k0 < K; k0 += 16) {
        #pragma unroll
        for (int i = 0; i < 2; i++) {
            int s   = tid + 256 * i;      // 512 float4 slots per operand tile
            int row = s >> 2;             // 0..127
            int kq  = (s & 3) << 2;       // 0,4,8,12
            float4 av = *(const float4*)&A[(size_t)(bm + row) * K + k0 + kq];
            At[kq+0][row] = av.x; At[kq+1][row] = av.y;
            At[kq+2][row] = av.z; At[kq+3][row] = av.w;
            float4 bv = *(const float4*)&B[(size_t)(bn + row) * K + k0 + kq];
            Bt[kq+0][row] = bv.x; Bt[kq+1][row] = bv.y;
            Bt[kq+2][row] = bv.z; Bt[kq+3][row] = bv.w;
        }
        __syncthreads();

        #pragma unroll
        for (int k = 0; k < 16; k++) {
            float a[8], bb[8];
            *(float4*)(a)    = *(float4*)&At[k][ty*8];
            *(float4*)(a+4)  = *(float4*)&At[k][ty*8+4];
            *(float4*)(bb)   = *(float4*)&Bt[k][tx*8];
            *(float4*)(bb+4) = *(float4*)&Bt[k][tx*8+4];
            #pragma unroll
            for (int i = 0; i < 8; i++)
                #pragma unroll
                for (int j = 0; j < 8; j++)
                    acc[i][j] = fmaf(a[i], bb[j], acc[i][j]);
        }
        __syncthreads();
    }

    #pragma unroll
    for (int i = 0; i < 8; i++) {
        size_t off = (size_t)(bm + ty*8 + i) * N + bn + tx*8;
        #pragma unroll
        for (int jj = 0; jj < 2; jj++) {
            float4 r;
            r.x = acc[i][jj*4+0]; r.y = acc[i][jj*4+1];
            r.z = acc[i][jj*4+2]; r.w = acc[i][jj*4+3];
            if (ADD) {
                float4 ad = *(const float4*)&Add[off + jj*4];
                r.x += ad.x; r.y += ad.y; r.z += ad.z; r.w += ad.w;
            }
            *(float4*)&C[off + jj*4] = r;
        }
    }
}

// ================= Flash attention (fp32, online softmax) =================
// grid (SEQ/64, BATCH, NH); block 256 threads.
// Block handles 64 query rows of one (b, head); loops over 32 key tiles (64).
// Thread (ty,tx) in 16x16 grid owns a 4(row) x 4(col/dim) microtile.
// smem: Qs[64][68] natural, Kt[64 k][68 c] transposed, Vs[64 c][68 d] natural,
//       Ps[64 r][65 c] natural, rowm[64], rowl[64].
__global__ void __launch_bounds__(256) attn_kernel(
    const float* __restrict__ q, const float* __restrict__ kv,
    float* __restrict__ vec)
{
    extern __shared__ float sm[];
    float* Qs   = sm;                 // 64*68
    float* Kt   = Qs + 64*68;         // 64*68
    float* Vs   = Kt + 64*68;         // 64*68
    float* Ps   = Vs + 64*68;         // 64*65
    float* rowm = Ps + 64*65;         // 64
    float* rowl = rowm + 64;          // 64

    const int tid = threadIdx.x;
    const int tx = tid & 15, ty = tid >> 4;
    const int i0 = blockIdx.x * 64;
    const int b  = blockIdx.y;
    const int n  = blockIdx.z;
    const int r0 = ty * 4, c0 = tx * 4;

    // load 64x64 Q tile (natural layout; scalar reads later)
    #pragma unroll
    for (int i = 0; i < 4; i++) {
        int s   = tid + 256 * i;       // 1024 float4 slots
        int row = s >> 4;              // 0..63
        int kq  = (s & 15) << 2;       // 0..60
        const float* src = q + (size_t)((i0 + row) * 2 + b) * 1024 + n * 64 + kq;
        *(float4*)&Qs[row * 68 + kq] = *(const float4*)src;
    }
    if (tid < 64) { rowm[tid] = -1e30f; rowl[tid] = 0.f; }

    float acc[4][4] = {};

    for (int j0 = 0; j0 < SEQ; j0 += 64) {
        __syncthreads();   // prev PV done (and Q load visible on first iter)
        // load K (transposed into Kt) and V (natural into Vs)
        #pragma unroll
        for (int i = 0; i < 4; i++) {
            int s   = tid + 256 * i;
            int row = s >> 4;
            int kq  = (s & 15) << 2;
            const float* base = kv + (size_t)((j0 + row) * 2 + b) * 2048 + n * 64 + kq;
            float4 kvv = *(const float4*)base;
            Kt[(kq+0)*68 + row] = kvv.x;
            Kt[(kq+1)*68 + row] = kvv.y;
            Kt[(kq+2)*68 + row] = kvv.z;
            Kt[(kq+3)*68 + row] = kvv.w;
            *(float4*)&Vs[row * 68 + kq] = *(const float4*)(base + 1024);
        }
        __syncthreads();

        // scores S = Q K^T (4x4 per thread)
        float s4[4][4] = {};
        #pragma unroll 8
        for (int k = 0; k < 64; k++) {
            float4 kk = *(float4*)&Kt[k * 68 + c0];
            float q0 = Qs[(r0+0)*68 + k];
            float q1 = Qs[(r0+1)*68 + k];
            float q2 = Qs[(r0+2)*68 + k];
            float q3 = Qs[(r0+3)*68 + k];
            s4[0][0] += q0*kk.x; s4[0][1] += q0*kk.y; s4[0][2] += q0*kk.z; s4[0][3] += q0*kk.w;
            s4[1][0] += q1*kk.x; s4[1][1] += q1*kk.y; s4[1][2] += q1*kk.z; s4[1][3] += q1*kk.w;
            s4[2][0] += q2*kk.x; s4[2][1] += q2*kk.y; s4[2][2] += q2*kk.z; s4[2][3] += q2*kk.w;
            s4[3][0] += q3*kk.x; s4[3][1] += q3*kk.y; s4[3][2] += q3*kk.z; s4[3][3] += q3*kk.w;
        }

        // online softmax per row group (row r handled by 16 lanes of one warp)
        #pragma unroll
        for (int ri = 0; ri < 4; ri++) {
            float v0 = s4[ri][0] * 0.125f;
            float v1 = s4[ri][1] * 0.125f;
            float v2 = s4[ri][2] * 0.125f;
            float v3 = s4[ri][3] * 0.125f;
            float tmax = fmaxf(fmaxf(v0, v1), fmaxf(v2, v3));
            #pragma unroll
            for (int off = 8; off; off >>= 1)
                tmax = fmaxf(tmax, __shfl_xor_sync(0xffffffffu, tmax, off));
            int r = r0 + ri;
            float mold = rowm[r];
            float mnew = fmaxf(mold, tmax);
            float p0 = __expf(v0 - mnew);
            float p1 = __expf(v1 - mnew);
            float p2 = __expf(v2 - mnew);
            float p3 = __expf(v3 - mnew);
            float psum = p0 + p1 + p2 + p3;
            #pragma unroll
            for (int off = 8; off; off >>= 1)
                psum += __shfl_xor_sync(0xffffffffu, psum, off);
            float alpha = __expf(mold - mnew);
            if (tx == 0) { rowl[r] = rowl[r] * alpha + psum; rowm[r] = mnew; }
            acc[ri][0] *= alpha; acc[ri][1] *= alpha;
            acc[ri][2] *= alpha; acc[ri][3] *= alpha;
            Ps[r*65 + c0+0] = p0; Ps[r*65 + c0+1] = p1;
            Ps[r*65 + c0+2] = p2; Ps[r*65 + c0+3] = p3;
        }
        __syncthreads();

        // acc += P @ V
        #pragma unroll 8
        for (int c = 0; c < 64; c++) {
            float4 vv = *(float4*)&Vs[c * 68 + c0];
            float p0 = Ps[(r0+0)*65 + c];
            float p1 = Ps[(r0+1)*65 + c];
            float p2 = Ps[(r0+2)*65 + c];
            float p3 = Ps[(r0+3)*65 + c];
            acc[0][0] += p0*vv.x; acc[0][1] += p0*vv.y; acc[0][2] += p0*vv.z; acc[0][3] += p0*vv.w;
            acc[1][0] += p1*vv.x; acc[1][1] += p1*vv.y; acc[1][2] += p1*vv.z; acc[1][3] += p1*vv.w;
            acc[2][0] += p2*vv.x; acc[2][1] += p2*vv.y; acc[2][2] += p2*vv.z; acc[2][3] += p2*vv.w;
            acc[3][0] += p3*vv.x; acc[3][1] += p3*vv.y; acc[3][2] += p3*vv.z; acc[3][3] += p3*vv.w;
        }
    }
    __syncthreads();

    #pragma unroll
    for (int ri = 0; ri < 4; ri++) {
        float inv = 1.f / rowl[r0 + ri];
        float4 o;
        o.x = acc[ri][0]*inv; o.y = acc[ri][1]*inv;
        o.z = acc[ri][2]*inv; o.w = acc[ri][3]*inv;
        float* dst = vec + (size_t)((i0 + r0 + ri) * 2 + b) * 1024 + n * 64 + c0;
        *(float4*)dst = o;
    }
}

// ================= LayerNorm (block per token row of 1024) ================
__device__ __forceinline__ void block_stats(float4 v, int t, float& mean, float& rstd)
{
    __shared__ float as[8], aq[8];
    float s  = v.x + v.y + v.z + v.w;
    float ss = v.x*v.x + v.y*v.y + v.z*v.z + v.w*v.w;
    #pragma unroll
    for (int off = 16; off; off >>= 1) {
        s  += __shfl_xor_sync(0xffffffffu, s, off);
        ss += __shfl_xor_sync(0xffffffffu, ss, off);
    }
    if ((t & 31) == 0) { as[t >> 5] = s; aq[t >> 5] = ss; }
    __syncthreads();
    s = 0.f; ss = 0.f;
    #pragma unroll
    for (int w = 0; w < 8; w++) { s += as[w]; ss += aq[w]; }
    mean = s * (1.f / 1024.f);
    float var = ss * (1.f / 1024.f) - mean * mean;
    rstd = rsqrtf(var + 1e-5f);
}

__global__ void __launch_bounds__(256) ln_kernel(
    const float* __restrict__ x, const float* __restrict__ g,
    const float* __restrict__ bt, float* __restrict__ y)
{
    int row = blockIdx.x;
    int t = threadIdx.x;
    float4 v = *(const float4*)&x[(size_t)row * 1024 + t * 4];
    float mean, rstd;
    block_stats(v, t, mean, rstd);
    float4 gv = *(const float4*)&g[t * 4];
    float4 bv = *(const float4*)&bt[t * 4];
    float4 o;
    o.x = (v.x - mean) * rstd * gv.x + bv.x;
    o.y = (v.y - mean) * rstd * gv.y + bv.y;
    o.z = (v.z - mean) * rstd * gv.z + bv.z;
    o.w = (v.w - mean) * rstd * gv.w + bv.w;
    *(float4*)&y[(size_t)row * 1024 + t * 4] = o;
}

// LN2 fused with final: out = 2*LN(x) + pe[b], b = row % 2 (token = i*B + b)
__global__ void __launch_bounds__(256) ln_final_kernel(
    const float* __restrict__ x, const float* __restrict__ g,
    const float* __restrict__ bt, float* __restrict__ y)
{
    int row = blockIdx.x;
    int t = threadIdx.x;
    float4 v = *(const float4*)&x[(size_t)row * 1024 + t * 4];
    float mean, rstd;
    block_stats(v, t, mean, rstd);
    float4 gv = *(const float4*)&g[t * 4];
    float4 bv = *(const float4*)&bt[t * 4];
    float ln[4] = {
        (v.x - mean) * rstd * gv.x + bv.x,
        (v.y - mean) * rstd * gv.y + bv.y,
        (v.z - mean) * rstd * gv.z + bv.z,
        (v.w - mean) * rstd * gv.w + bv.w
    };
    float bcol = (float)(row & 1);
    float o4[4];
    #pragma unroll
    for (int j = 0; j < 4; j++) {
        int d = t * 4 + j;
        // freqs = 10000^(-(d&~1)/1024); pe = sin(b*f) for even d, cos for odd
        float e = (float)(d & ~1) * (1.f / 1024.f);
        float freq = __expf(-9.210340371976184f * e);  // ln(10000)
        float ang = bcol * freq;
        float pe = (d & 1) ? cosf(ang) : sinf(ang);
        o4[j] = 2.f * ln[j] + pe;
    }
    float4 o; o.x = o4[0]; o.y = o4[1]; o.z = o4[2]; o.w = o4[3];
    *(float4*)&y[(size_t)row * 1024 + t * 4] = o;
}

// ================= launch ==================================================
extern "C" void kernel_launch(void* const* d_in, const int* in_sizes, int n_in,
                              void* d_out, int out_size)
{
    const float* dec = (const float*)d_in[0];
    const float* Wq  = (const float*)d_in[1];
    const float* Wkv = (const float*)d_in[2];
    const float* Wo  = (const float*)d_in[3];
    const float* g1  = (const float*)d_in[4];
    const float* b1  = (const float*)d_in[5];
    const float* Wff = (const float*)d_in[6];
    const float* g2  = (const float*)d_in[7];
    const float* b2  = (const float*)d_in[8];
    float* out = (float*)d_out;

    float *q, *kv, *vec, *h0, *h1, *f0;
    cudaGetSymbolAddress((void**)&q,   g_q);
    cudaGetSymbolAddress((void**)&kv,  g_kv);
    cudaGetSymbolAddress((void**)&vec, g_vec);
    cudaGetSymbolAddress((void**)&h0,  g_h0);
    cudaGetSymbolAddress((void**)&h1,  g_h1);
    cudaGetSymbolAddress((void**)&f0,  g_f0);

    const int ATT_SMEM = (64*68*3 + 64*65 + 128) * (int)sizeof(float);  // ~69.9 KB
    cudaFuncSetAttribute(attn_kernel,
                         cudaFuncAttributeMaxDynamicSharedMemorySize, ATT_SMEM);

    // q = dec @ Wq^T   [4096,1024]
    gemm_nt<false><<<dim3(1024/128, 4096/128), 256>>>(dec, Wq, nullptr, q,
                                                      MTOK, 1024, 1024);
    // kv = dec @ Wkv^T [4096,2048]
    gemm_nt<false><<<dim3(2048/128, 4096/128), 256>>>(dec, Wkv, nullptr, kv,
                                                      MTOK, 2048, 1024);
    // attention -> vec [4096,1024]
    attn_kernel<<<dim3(SEQ/64, BATCH, NH), 256, ATT_SMEM>>>(q, kv, vec);
    // h0 = dec + vec @ Wo^T
    gemm_nt<true><<<dim3(1024/128, 4096/128), 256>>>(vec, Wo, dec, h0,
                                                     MTOK, 1024, 1024);
    // h1 = LN(h0)
    ln_kernel<<<MTOK, 256>>>(h0, g1, b1, h1);
    // f0 = h1 + h1 @ Wff^T
    gemm_nt<true><<<dim3(1024/128, 4096/128), 256>>>(h1, Wff, h1, f0,
                                                     MTOK, 1024, 1024);
    // out = 2*LN(f0) + pe[b]
    ln_final_kernel<<<MTOK, 256>>>(f0, g2, b2, out);
}

// round 2
// speedup vs baseline: 1.4234x; 1.4234x over previous
#include <cuda_runtime.h>
#include <cuda_bf16.h>
#include <cstdint>

// Problem constants
#define SEQ   2048
#define BATCH 2
#define DM    1024
#define NH    16
#define DH    64
#define MTOK  (SEQ*BATCH)   // 4096 token rows

// ---------------- scratch (device globals: allocation-free rule) ----------
__device__ float g_q  [MTOK * DM];        // 16 MB
__device__ float g_kv [MTOK * 2 * DM];    // 32 MB
__device__ float g_vec[MTOK * DM];        // 16 MB
__device__ float g_h0 [MTOK * DM];
__device__ float g_h1 [MTOK * DM];
__device__ float g_f0 [MTOK * DM];

// ===================== tensor-core GEMM (split-bf16 3x) ====================
// C[M,N] = A[M,K] * B[N,K]^T (+ optional Add), fp32 in/out, internally
// hi/lo bf16 split with 3 MMAs (hh, hl, lh) -> ~1.5e-5 relative accuracy.
// Block tile 128x128x32, 8 warps (2x4), warp tile 64x32, m16n8k16 mma.

__device__ __forceinline__ void ldsm_x4(uint32_t r[4], uint32_t addr) {
    asm volatile("ldmatrix.sync.aligned.m8n8.x4.shared.b16 {%0,%1,%2,%3}, [%4];\n"
                 : "=r"(r[0]), "=r"(r[1]), "=r"(r[2]), "=r"(r[3]) : "r"(addr));
}

__device__ __forceinline__ void mma16816(float c[4],
                                         uint32_t a0, uint32_t a1, uint32_t a2, uint32_t a3,
                                         uint32_t b0, uint32_t b1) {
    asm volatile(
        "mma.sync.aligned.m16n8k16.row.col.f32.bf16.bf16.f32 "
        "{%0,%1,%2,%3}, {%4,%5,%6,%7}, {%8,%9}, {%0,%1,%2,%3};\n"
        : "+f"(c[0]), "+f"(c[1]), "+f"(c[2]), "+f"(c[3])
        : "r"(a0), "r"(a1), "r"(a2), "r"(a3), "r"(b0), "r"(b1));
}

// smem plane geometry: 128 rows x 32 cols bf16, row stride 40 (80B, LDSM-conflict-free)
#define GP_STRIDE 40
#define GP_ELEMS  (128 * GP_STRIDE)     // elements per plane
#define GP_BYTES  (GP_ELEMS * 2)        // 10240
#define GBUF_BYTES (4 * GP_BYTES)       // Ahi,Alo,Bhi,Blo
#define GSMEM_BYTES (2 * GBUF_BYTES)    // double buffer = 81920

// convert float4 -> hi pack (2x u32) + lo pack (2x u32)
__device__ __forceinline__ void split4(float4 v, uint32_t hp[2], uint32_t lp[2]) {
    uint32_t u0 = __float_as_uint(v.x), u1 = __float_as_uint(v.y);
    uint32_t u2 = __float_as_uint(v.z), u3 = __float_as_uint(v.w);
    hp[0] = __byte_perm(u0, u1, 0x7632);
    hp[1] = __byte_perm(u2, u3, 0x7632);
    float r0 = v.x - __uint_as_float(u0 & 0xffff0000u);
    float r1 = v.y - __uint_as_float(u1 & 0xffff0000u);
    float r2 = v.z - __uint_as_float(u2 & 0xffff0000u);
    float r3 = v.w - __uint_as_float(u3 & 0xffff0000u);
    __nv_bfloat162 l01 = __floats2bfloat162_rn(r0, r1);
    __nv_bfloat162 l23 = __floats2bfloat162_rn(r2, r3);
    lp[0] = *(uint32_t*)&l01;
    lp[1] = *(uint32_t*)&l23;
}

template<bool ADD>
__global__ void __launch_bounds__(256) gemm_bf3(
    const float* __restrict__ A, const float* __restrict__ B,
    const float* __restrict__ Add, float* __restrict__ C,
    int M, int N, int K)
{
    extern __shared__ __align__(16) unsigned char smraw[];
    uint32_t sbase = (uint32_t)__cvta_generic_to_shared(smraw);

    const int tid  = threadIdx.x;
    const int lane = tid & 31;
    const int wid  = tid >> 5;
    const int wm   = wid >> 2;        // 0..1
    const int wn   = wid & 3;         // 0..3
    const int bm   = blockIdx.y * 128;
    const int bn   = blockIdx.x * 128;

    float acc[4][4][4] = {};

    // per-thread global load coordinates (4 float4 per operand per tile)
    int lrow[4], lcol[4];
    #pragma unroll
    for (int i = 0; i < 4; i++) {
        int s = tid + 256 * i;
        lrow[i] = s >> 3;
        lcol[i] = (s & 7) * 4;
    }

    float4 ra[4], rb[4];
    auto load_tiles = [&](int k0) {
        #pragma unroll
        for (int i = 0; i < 4; i++)
            ra[i] = *(const float4*)&A[(size_t)(bm + lrow[i]) * K + k0 + lcol[i]];
        #pragma unroll
        for (int i = 0; i < 4; i++)
            rb[i] = *(const float4*)&B[(size_t)(bn + lrow[i]) * K + k0 + lcol[i]];
    };
    auto sts_tiles = [&](int buf) {
        uint32_t* base = (uint32_t*)(smraw + buf * GBUF_BYTES);
        #pragma unroll
        for (int i = 0; i < 4; i++) {
            uint32_t hp[2], lp[2];
            int eo = (lrow[i] * GP_STRIDE + lcol[i]) >> 1;   // u32 index
            split4(ra[i], hp, lp);
            base[eo]                     = hp[0];
            base[eo + 1]                 = hp[1];
            base[eo + (GP_BYTES >> 2)]       = lp[0];
            base[eo + (GP_BYTES >> 2) + 1]   = lp[1];
            split4(rb[i], hp, lp);
            base[eo + 2 * (GP_BYTES >> 2)]     = hp[0];
            base[eo + 2 * (GP_BYTES >> 2) + 1] = hp[1];
            base[eo + 3 * (GP_BYTES >> 2)]     = lp[0];
            base[eo + 3 * (GP_BYTES >> 2) + 1] = lp[1];
        }
    };

    // LDSM per-lane address pieces
    const uint32_t arow = lane & 15;
    const uint32_t acol = ((lane >> 4) & 1) * 8;
    const uint32_t brow = (lane & 7) + ((lane >> 4) & 1) * 8;
    const uint32_t bcol = ((lane >> 3) & 1) * 8;

    auto compute = [&](int buf) {
        uint32_t base = sbase + buf * GBUF_BYTES;
        #pragma unroll
        for (int s = 0; s < 2; s++) {
            uint32_t ah[4][4], al[4][4], bh[2][4], bl[2][4];
            #pragma unroll
            for (int mt = 0; mt < 4; mt++) {
                uint32_t off = (((wm * 64 + mt * 16 + arow) * GP_STRIDE) + acol + s * 16) << 1;
                ldsm_x4(ah[mt], base + off);
                ldsm_x4(al[mt], base + GP_BYTES + off);
            }
            #pragma unroll
            for (int np = 0; np < 2; np++) {
                uint32_t off = (((wn * 32 + np * 16 + brow) * GP_STRIDE) + bcol + s * 16) << 1;
                ldsm_x4(bh[np], base + 2 * GP_BYTES + off);
                ldsm_x4(bl[np], base + 3 * GP_BYTES + off);
            }
            #pragma unroll
            for (int mt = 0; mt < 4; mt++)
                #pragma unroll
                for (int nt = 0; nt < 4; nt++) {
                    int p = nt >> 1, q = (nt & 1) * 2;
                    mma16816(acc[mt][nt], ah[mt][0], ah[mt][1], ah[mt][2], ah[mt][3],
                             bh[p][q], bh[p][q + 1]);
                    mma16816(acc[mt][nt], ah[mt][0], ah[mt][1], ah[mt][2], ah[mt][3],
                             bl[p][q], bl[p][q + 1]);
                    mma16816(acc[mt][nt], al[mt][0], al[mt][1], al[mt][2], al[mt][3],
                             bh[p][q], bh[p][q + 1]);
                }
        }
    };

    // pipeline: prologue
    load_tiles(0);
    sts_tiles(0);
    __syncthreads();

    for (int k0 = 0; k0 < K; k0 += 32) {
        int cur = (k0 >> 5) & 1;
        bool more = (k0 + 32 < K);
        if (more) load_tiles(k0 + 32);
        compute(cur);
        if (more) sts_tiles(cur ^ 1);
        __syncthreads();
    }

    // epilogue
    #pragma unroll
    for (int mt = 0; mt < 4; mt++) {
        #pragma unroll
        for (int nt = 0; nt < 4; nt++) {
            int row0 = bm + wm * 64 + mt * 16 + (lane >> 2);
            int col  = bn + wn * 32 + nt * 8 + (lane & 3) * 2;
            size_t o0 = (size_t)row0 * N + col;
            size_t o1 = (size_t)(row0 + 8) * N + col;
            float2 r0 = make_float2(acc[mt][nt][0], acc[mt][nt][1]);
            float2 r1 = make_float2(acc[mt][nt][2], acc[mt][nt][3]);
            if (ADD) {
                float2 a0 = *(const float2*)&Add[o0];
                float2 a1 = *(const float2*)&Add[o1];
                r0.x += a0.x; r0.y += a0.y;
                r1.x += a1.x; r1.y += a1.y;
            }
            *(float2*)&C[o0] = r0;
            *(float2*)&C[o1] = r1;
        }
    }
}

// ================= Flash attention (fp32, online softmax) — unchanged =====
__global__ void __launch_bounds__(256) attn_kernel(
    const float* __restrict__ q, const float* __restrict__ kv,
    float* __restrict__ vec)
{
    extern __shared__ float sm[];
    float* Qs   = sm;                 // 64*68
    float* Kt   = Qs + 64*68;         // 64*68
    float* Vs   = Kt + 64*68;         // 64*68
    float* Ps   = Vs + 64*68;         // 64*65
    float* rowm = Ps + 64*65;         // 64
    float* rowl = rowm + 64;          // 64

    const int tid = threadIdx.x;
    const int tx = tid & 15, ty = tid >> 4;
    const int i0 = blockIdx.x * 64;
    const int b  = blockIdx.y;
    const int n  = blockIdx.z;
    const int r0 = ty * 4, c0 = tx * 4;

    #pragma unroll
    for (int i = 0; i < 4; i++) {
        int s   = tid + 256 * i;
        int row = s >> 4;
        int kq  = (s & 15) << 2;
        const float* src = q + (size_t)((i0 + row) * 2 + b) * 1024 + n * 64 + kq;
        *(float4*)&Qs[row * 68 + kq] = *(const float4*)src;
    }
    if (tid < 64) { rowm[tid] = -1e30f; rowl[tid] = 0.f; }

    float acc[4][4] = {};

    for (int j0 = 0; j0 < SEQ; j0 += 64) {
        __syncthreads();
        #pragma unroll
        for (int i = 0; i < 4; i++) {
            int s   = tid + 256 * i;
            int row = s >> 4;
            int kq  = (s & 15) << 2;
            const float* base = kv + (size_t)((j0 + row) * 2 + b) * 2048 + n * 64 + kq;
            float4 kvv = *(const float4*)base;
            Kt[(kq+0)*68 + row] = kvv.x;
            Kt[(kq+1)*68 + row] = kvv.y;
            Kt[(kq+2)*68 + row] = kvv.z;
            Kt[(kq+3)*68 + row] = kvv.w;
            *(float4*)&Vs[row * 68 + kq] = *(const float4*)(base + 1024);
        }
        __syncthreads();

        float s4[4][4] = {};
        #pragma unroll 8
        for (int k = 0; k < 64; k++) {
            float4 kk = *(float4*)&Kt[k * 68 + c0];
            float q0 = Qs[(r0+0)*68 + k];
            float q1 = Qs[(r0+1)*68 + k];
            float q2 = Qs[(r0+2)*68 + k];
            float q3 = Qs[(r0+3)*68 + k];
            s4[0][0] += q0*kk.x; s4[0][1] += q0*kk.y; s4[0][2] += q0*kk.z; s4[0][3] += q0*kk.w;
            s4[1][0] += q1*kk.x; s4[1][1] += q1*kk.y; s4[1][2] += q1*kk.z; s4[1][3] += q1*kk.w;
            s4[2][0] += q2*kk.x; s4[2][1] += q2*kk.y; s4[2][2] += q2*kk.z; s4[2][3] += q2*kk.w;
            s4[3][0] += q3*kk.x; s4[3][1] += q3*kk.y; s4[3][2] += q3*kk.z; s4[3][3] += q3*kk.w;
        }

        #pragma unroll
        for (int ri = 0; ri < 4; ri++) {
            float v0 = s4[ri][0] * 0.125f;
            float v1 = s4[ri][1] * 0.125f;
            float v2 = s4[ri][2] * 0.125f;
            float v3 = s4[ri][3] * 0.125f;
            float tmax = fmaxf(fmaxf(v0, v1), fmaxf(v2, v3));
            #pragma unroll
            for (int off = 8; off; off >>= 1)
                tmax = fmaxf(tmax, __shfl_xor_sync(0xffffffffu, tmax, off));
            int r = r0 + ri;
            float mold = rowm[r];
            float mnew = fmaxf(mold, tmax);
            float p0 = __expf(v0 - mnew);
            float p1 = __expf(v1 - mnew);
            float p2 = __expf(v2 - mnew);
            float p3 = __expf(v3 - mnew);
            float psum = p0 + p1 + p2 + p3;
            #pragma unroll
            for (int off = 8; off; off >>= 1)
                psum += __shfl_xor_sync(0xffffffffu, psum, off);
            float alpha = __expf(mold - mnew);
            if (tx == 0) { rowl[r] = rowl[r] * alpha + psum; rowm[r] = mnew; }
            acc[ri][0] *= alpha; acc[ri][1] *= alpha;
            acc[ri][2] *= alpha; acc[ri][3] *= alpha;
            Ps[r*65 + c0+0] = p0; Ps[r*65 + c0+1] = p1;
            Ps[r*65 + c0+2] = p2; Ps[r*65 + c0+3] = p3;
        }
        __syncthreads();

        #pragma unroll 8
        for (int c = 0; c < 64; c++) {
            float4 vv = *(float4*)&Vs[c * 68 + c0];
            float p0 = Ps[(r0+0)*65 + c];
            float p1 = Ps[(r0+1)*65 + c];
            float p2 = Ps[(r0+2)*65 + c];
            float p3 = Ps[(r0+3)*65 + c];
            acc[0][0] += p0*vv.x; acc[0][1] += p0*vv.y; acc[0][2] += p0*vv.z; acc[0][3] += p0*vv.w;
            acc[1][0] += p1*vv.x; acc[1][1] += p1*vv.y; acc[1][2] += p1*vv.z; acc[1][3] += p1*vv.w;
            acc[2][0] += p2*vv.x; acc[2][1] += p2*vv.y; acc[2][2] += p2*vv.z; acc[2][3] += p2*vv.w;
            acc[3][0] += p3*vv.x; acc[3][1] += p3*vv.y; acc[3][2] += p3*vv.z; acc[3][3] += p3*vv.w;
        }
    }
    __syncthreads();

    #pragma unroll
    for (int ri = 0; ri < 4; ri++) {
        float inv = 1.f / rowl[r0 + ri];
        float4 o;
        o.x = acc[ri][0]*inv; o.y = acc[ri][1]*inv;
        o.z = acc[ri][2]*inv; o.w = acc[ri][3]*inv;
        float* dst = vec + (size_t)((i0 + r0 + ri) * 2 + b) * 1024 + n * 64 + c0;
        *(float4*)dst = o;
    }
}

// ================= LayerNorm kernels — unchanged ==========================
__device__ __forceinline__ void block_stats(float4 v, int t, float& mean, float& rstd)
{
    __shared__ float as[8], aq[8];
    float s  = v.x + v.y + v.z + v.w;
    float ss = v.x*v.x + v.y*v.y + v.z*v.z + v.w*v.w;
    #pragma unroll
    for (int off = 16; off; off >>= 1) {
        s  += __shfl_xor_sync(0xffffffffu, s, off);
        ss += __shfl_xor_sync(0xffffffffu, ss, off);
    }
    if ((t & 31) == 0) { as[t >> 5] = s; aq[t >> 5] = ss; }
    __syncthreads();
    s = 0.f; ss = 0.f;
    #pragma unroll
    for (int w = 0; w < 8; w++) { s += as[w]; ss += aq[w]; }
    mean = s * (1.f / 1024.f);
    float var = ss * (1.f / 1024.f) - mean * mean;
    rstd = rsqrtf(var + 1e-5f);
}

__global__ void __launch_bounds__(256) ln_kernel(
    const float* __restrict__ x, const float* __restrict__ g,
    const float* __restrict__ bt, float* __restrict__ y)
{
    int row = blockIdx.x;
    int t = threadIdx.x;
    float4 v = *(const float4*)&x[(size_t)row * 1024 + t * 4];
    float mean, rstd;
    block_stats(v, t, mean, rstd);
    float4 gv = *(const float4*)&g[t * 4];
    float4 bv = *(const float4*)&bt[t * 4];
    float4 o;
    o.x = (v.x - mean) * rstd * gv.x + bv.x;
    o.y = (v.y - mean) * rstd * gv.y + bv.y;
    o.z = (v.z - mean) * rstd * gv.z + bv.z;
    o.w = (v.w - mean) * rstd * gv.w + bv.w;
    *(float4*)&y[(size_t)row * 1024 + t * 4] = o;
}

__global__ void __launch_bounds__(256) ln_final_kernel(
    const float* __restrict__ x, const float* __restrict__ g,
    const float* __restrict__ bt, float* __restrict__ y)
{
    int row = blockIdx.x;
    int t = threadIdx.x;
    float4 v = *(const float4*)&x[(size_t)row * 1024 + t * 4];
    float mean, rstd;
    block_stats(v, t, mean, rstd);
    float4 gv = *(const float4*)&g[t * 4];
    float4 bv = *(const float4*)&bt[t * 4];
    float ln[4] = {
        (v.x - mean) * rstd * gv.x + bv.x,
        (v.y - mean) * rstd * gv.y + bv.y,
        (v.z - mean) * rstd * gv.z + bv.z,
        (v.w - mean) * rstd * gv.w + bv.w
    };
    float bcol = (float)(row & 1);
    float o4[4];
    #pragma unroll
    for (int j = 0; j < 4; j++) {
        int d = t * 4 + j;
        float e = (float)(d & ~1) * (1.f / 1024.f);
        float freq = __expf(-9.210340371976184f * e);  // ln(10000)
        float ang = bcol * freq;
        float pe = (d & 1) ? cosf(ang) : sinf(ang);
        o4[j] = 2.f * ln[j] + pe;
    }
    float4 o; o.x = o4[0]; o.y = o4[1]; o.z = o4[2]; o.w = o4[3];
    *(float4*)&y[(size_t)row * 1024 + t * 4] = o;
}

// ================= launch ==================================================
extern "C" void kernel_launch(void* const* d_in, const int* in_sizes, int n_in,
                              void* d_out, int out_size)
{
    const float* dec = (const float*)d_in[0];
    const float* Wq  = (const float*)d_in[1];
    const float* Wkv = (const float*)d_in[2];
    const float* Wo  = (const float*)d_in[3];
    const float* g1  = (const float*)d_in[4];
    const float* b1  = (const float*)d_in[5];
    const float* Wff = (const float*)d_in[6];
    const float* g2  = (const float*)d_in[7];
    const float* b2  = (const float*)d_in[8];
    float* out = (float*)d_out;

    float *q, *kv, *vec, *h0, *h1, *f0;
    cudaGetSymbolAddress((void**)&q,   g_q);
    cudaGetSymbolAddress((void**)&kv,  g_kv);
    cudaGetSymbolAddress((void**)&vec, g_vec);
    cudaGetSymbolAddress((void**)&h0,  g_h0);
    cudaGetSymbolAddress((void**)&h1,  g_h1);
    cudaGetSymbolAddress((void**)&f0,  g_f0);

    const int ATT_SMEM = (64*68*3 + 64*65 + 128) * (int)sizeof(float);  // ~69.9 KB
    cudaFuncSetAttribute(attn_kernel,
                         cudaFuncAttributeMaxDynamicSharedMemorySize, ATT_SMEM);
    cudaFuncSetAttribute(gemm_bf3<false>,
                         cudaFuncAttributeMaxDynamicSharedMemorySize, GSMEM_BYTES);
    cudaFuncSetAttribute(gemm_bf3<true>,
                         cudaFuncAttributeMaxDynamicSharedMemorySize, GSMEM_BYTES);

    // q = dec @ Wq^T   [4096,1024]
    gemm_bf3<false><<<dim3(1024/128, 4096/128), 256, GSMEM_BYTES>>>(
        dec, Wq, nullptr, q, MTOK, 1024, 1024);
    // kv = dec @ Wkv^T [4096,2048]
    gemm_bf3<false><<<dim3(2048/128, 4096/128), 256, GSMEM_BYTES>>>(
        dec, Wkv, nullptr, kv, MTOK, 2048, 1024);
    // attention -> vec [4096,1024]
    attn_kernel<<<dim3(SEQ/64, BATCH, NH), 256, ATT_SMEM>>>(q, kv, vec);
    // h0 = dec + vec @ Wo^T
    gemm_bf3<true><<<dim3(1024/128, 4096/128), 256, GSMEM_BYTES>>>(
        vec, Wo, dec, h0, MTOK, 1024, 1024);
    // h1 = LN(h0)
    ln_kernel<<<MTOK, 256>>>(h0, g1, b1, h1);
    // f0 = h1 + h1 @ Wff^T
    gemm_bf3<true><<<dim3(1024/128, 4096/128), 256, GSMEM_BYTES>>>(
        h1, Wff, h1, f0, MTOK, 1024, 1024);
    // out = 2*LN(f0) + pe[b]
    ln_final_kernel<<<MTOK, 256>>>(f0, g2, b2, out);
}

// round 3
// speedup vs baseline: 2.2589x; 1.5870x over previous
#include <cuda_runtime.h>
#include <cuda_bf16.h>
#include <cstdint>

// Problem constants
#define SEQ   2048
#define BATCH 2
#define DM    1024
#define NH    16
#define DH    64
#define MTOK  (SEQ*BATCH)   // 4096 token rows

// ---------------- scratch (device globals: allocation-free rule) ----------
__device__ float g_q  [MTOK * DM];
__device__ float g_kv [MTOK * 2 * DM];
__device__ float g_vec[MTOK * DM];
__device__ float g_h0 [MTOK * DM];
__device__ float g_h1 [MTOK * DM];
__device__ float g_f0 [MTOK * DM];

// ===================== common MMA helpers ==================================
__device__ __forceinline__ void ldsm_x4(uint32_t r[4], uint32_t addr) {
    asm volatile("ldmatrix.sync.aligned.m8n8.x4.shared.b16 {%0,%1,%2,%3}, [%4];\n"
                 : "=r"(r[0]), "=r"(r[1]), "=r"(r[2]), "=r"(r[3]) : "r"(addr));
}

__device__ __forceinline__ void mma16816(float c[4],
                                         uint32_t a0, uint32_t a1, uint32_t a2, uint32_t a3,
                                         uint32_t b0, uint32_t b1) {
    asm volatile(
        "mma.sync.aligned.m16n8k16.row.col.f32.bf16.bf16.f32 "
        "{%0,%1,%2,%3}, {%4,%5,%6,%7}, {%8,%9}, {%0,%1,%2,%3};\n"
        : "+f"(c[0]), "+f"(c[1]), "+f"(c[2]), "+f"(c[3])
        : "r"(a0), "r"(a1), "r"(a2), "r"(a3), "r"(b0), "r"(b1));
}

// split fp32 -> hi (truncated-to-bf16 bits) + lo (bf16_rn of residual)
__device__ __forceinline__ void split4(float4 v, uint32_t hp[2], uint32_t lp[2]) {
    uint32_t u0 = __float_as_uint(v.x), u1 = __float_as_uint(v.y);
    uint32_t u2 = __float_as_uint(v.z), u3 = __float_as_uint(v.w);
    hp[0] = __byte_perm(u0, u1, 0x7632);
    hp[1] = __byte_perm(u2, u3, 0x7632);
    float r0 = v.x - __uint_as_float(u0 & 0xffff0000u);
    float r1 = v.y - __uint_as_float(u1 & 0xffff0000u);
    float r2 = v.z - __uint_as_float(u2 & 0xffff0000u);
    float r3 = v.w - __uint_as_float(u3 & 0xffff0000u);
    __nv_bfloat162 l01 = __floats2bfloat162_rn(r0, r1);
    __nv_bfloat162 l23 = __floats2bfloat162_rn(r2, r3);
    lp[0] = *(uint32_t*)&l01;
    lp[1] = *(uint32_t*)&l23;
}

__device__ __forceinline__ uint32_t pack_hi2(float a, float b) {
    return __byte_perm(__float_as_uint(a), __float_as_uint(b), 0x7632);
}
__device__ __forceinline__ uint32_t pack_lo2(float a, float b) {
    float ra = a - __uint_as_float(__float_as_uint(a) & 0xffff0000u);
    float rb = b - __uint_as_float(__float_as_uint(b) & 0xffff0000u);
    __nv_bfloat162 l = __floats2bfloat162_rn(ra, rb);
    return *(uint32_t*)&l;
}

// ===================== tensor-core GEMM (split-bf16 3x) ====================
#define GP_STRIDE 40
#define GP_ELEMS  (128 * GP_STRIDE)
#define GP_BYTES  (GP_ELEMS * 2)        // 10240
#define GBUF_BYTES (4 * GP_BYTES)
#define GSMEM_BYTES (2 * GBUF_BYTES)    // 81920

template<bool ADD>
__global__ void __launch_bounds__(256) gemm_bf3(
    const float* __restrict__ A, const float* __restrict__ B,
    const float* __restrict__ Add, float* __restrict__ C,
    int M, int N, int K)
{
    extern __shared__ __align__(16) unsigned char smraw[];
    uint32_t sbase = (uint32_t)__cvta_generic_to_shared(smraw);

    const int tid  = threadIdx.x;
    const int lane = tid & 31;
    const int wid  = tid >> 5;
    const int wm   = wid >> 2;
    const int wn   = wid & 3;
    const int bm   = blockIdx.y * 128;
    const int bn   = blockIdx.x * 128;

    float acc[4][4][4] = {};

    int lrow[4], lcol[4];
    #pragma unroll
    for (int i = 0; i < 4; i++) {
        int s = tid + 256 * i;
        lrow[i] = s >> 3;
        lcol[i] = (s & 7) * 4;
    }

    float4 ra[4], rb[4];
    auto load_tiles = [&](int k0) {
        #pragma unroll
        for (int i = 0; i < 4; i++)
            ra[i] = *(const float4*)&A[(size_t)(bm + lrow[i]) * K + k0 + lcol[i]];
        #pragma unroll
        for (int i = 0; i < 4; i++)
            rb[i] = *(const float4*)&B[(size_t)(bn + lrow[i]) * K + k0 + lcol[i]];
    };
    auto sts_tiles = [&](int buf) {
        uint32_t* base = (uint32_t*)(smraw + buf * GBUF_BYTES);
        #pragma unroll
        for (int i = 0; i < 4; i++) {
            uint32_t hp[2], lp[2];
            int eo = (lrow[i] * GP_STRIDE + lcol[i]) >> 1;
            split4(ra[i], hp, lp);
            base[eo]                     = hp[0];
            base[eo + 1]                 = hp[1];
            base[eo + (GP_BYTES >> 2)]       = lp[0];
            base[eo + (GP_BYTES >> 2) + 1]   = lp[1];
            split4(rb[i], hp, lp);
            base[eo + 2 * (GP_BYTES >> 2)]     = hp[0];
            base[eo + 2 * (GP_BYTES >> 2) + 1] = hp[1];
            base[eo + 3 * (GP_BYTES >> 2)]     = lp[0];
            base[eo + 3 * (GP_BYTES >> 2) + 1] = lp[1];
        }
    };

    const uint32_t arow = lane & 15;
    const uint32_t acol = ((lane >> 4) & 1) * 8;
    const uint32_t brow = (lane & 7) + ((lane >> 4) & 1) * 8;
    const uint32_t bcol = ((lane >> 3) & 1) * 8;

    auto compute = [&](int buf) {
        uint32_t base = sbase + buf * GBUF_BYTES;
        #pragma unroll
        for (int s = 0; s < 2; s++) {
            uint32_t ah[4][4], al[4][4], bh[2][4], bl[2][4];
            #pragma unroll
            for (int mt = 0; mt < 4; mt++) {
                uint32_t off = (((wm * 64 + mt * 16 + arow) * GP_STRIDE) + acol + s * 16) << 1;
                ldsm_x4(ah[mt], base + off);
                ldsm_x4(al[mt], base + GP_BYTES + off);
            }
            #pragma unroll
            for (int np = 0; np < 2; np++) {
                uint32_t off = (((wn * 32 + np * 16 + brow) * GP_STRIDE) + bcol + s * 16) << 1;
                ldsm_x4(bh[np], base + 2 * GP_BYTES + off);
                ldsm_x4(bl[np], base + 3 * GP_BYTES + off);
            }
            #pragma unroll
            for (int mt = 0; mt < 4; mt++)
                #pragma unroll
                for (int nt = 0; nt < 4; nt++) {
                    int p = nt >> 1, q = (nt & 1) * 2;
                    mma16816(acc[mt][nt], ah[mt][0], ah[mt][1], ah[mt][2], ah[mt][3],
                             bh[p][q], bh[p][q + 1]);
                    mma16816(acc[mt][nt], ah[mt][0], ah[mt][1], ah[mt][2], ah[mt][3],
                             bl[p][q], bl[p][q + 1]);
                    mma16816(acc[mt][nt], al[mt][0], al[mt][1], al[mt][2], al[mt][3],
                             bh[p][q], bh[p][q + 1]);
                }
        }
    };

    load_tiles(0);
    sts_tiles(0);
    __syncthreads();

    for (int k0 = 0; k0 < K; k0 += 32) {
        int cur = (k0 >> 5) & 1;
        bool more = (k0 + 32 < K);
        if (more) load_tiles(k0 + 32);
        compute(cur);
        if (more) sts_tiles(cur ^ 1);
        __syncthreads();
    }

    #pragma unroll
    for (int mt = 0; mt < 4; mt++) {
        #pragma unroll
        for (int nt = 0; nt < 4; nt++) {
            int row0 = bm + wm * 64 + mt * 16 + (lane >> 2);
            int col  = bn + wn * 32 + nt * 8 + (lane & 3) * 2;
            size_t o0 = (size_t)row0 * N + col;
            size_t o1 = (size_t)(row0 + 8) * N + col;
            float2 r0 = make_float2(acc[mt][nt][0], acc[mt][nt][1]);
            float2 r1 = make_float2(acc[mt][nt][2], acc[mt][nt][3]);
            if (ADD) {
                float2 a0 = *(const float2*)&Add[o0];
                float2 a1 = *(const float2*)&Add[o1];
                r0.x += a0.x; r0.y += a0.y;
                r1.x += a1.x; r1.y += a1.y;
            }
            *(float2*)&C[o0] = r0;
            *(float2*)&C[o1] = r1;
        }
    }
}

// ================= Tensor-core flash attention (split-bf16 3x) ============
// Block: 128 query rows of one (b,head); 8 warps, warp = 16 rows.
// j-loop over 32 key tiles of 64. Q frags live in registers the whole loop.
// smem (36864 B, reused): stage 1: Qhi[128][72] + Qlo[128][72];
// stage 2 (per j-iter): Khi[64][72], Klo, Vthi[64][72] (V transposed), Vtlo.
#define SKS 72
#define APLANE (64 * SKS)               // elems per 64-row plane

__global__ void __launch_bounds__(256) attn_tc(
    const float* __restrict__ q, const float* __restrict__ kv,
    float* __restrict__ vec)
{
    __shared__ __align__(16) unsigned short sm[4 * APLANE];   // 36864 B
    uint32_t sbase = (uint32_t)__cvta_generic_to_shared(sm);
    uint32_t* sm32 = (uint32_t*)sm;

    const int tid  = threadIdx.x;
    const int lane = tid & 31;
    const int wid  = tid >> 5;
    const int i0   = blockIdx.x * 128;
    const int b    = blockIdx.y;
    const int n    = blockIdx.z;

    // ---- stage Q (128x64 fp32 -> hi/lo bf16 planes) ----
    #pragma unroll
    for (int i = 0; i < 8; i++) {
        int s   = tid + 256 * i;        // 2048 float4
        int row = s >> 4;               // 0..127
        int col = (s & 15) * 4;
        float4 v = *(const float4*)&q[(size_t)((i0 + row) * 2 + b) * 1024 + n * 64 + col];
        uint32_t hp[2], lp[2];
        split4(v, hp, lp);
        int eo = (row * SKS + col) >> 1;
        sm32[eo] = hp[0]; sm32[eo + 1] = hp[1];
        sm32[eo + APLANE] = lp[0]; sm32[eo + APLANE + 1] = lp[1];  // Qlo at +2 planes (128*SKS elems)
    }
    __syncthreads();

    // ---- Q fragments (A operand, 4 k-chunks of 16) ----
    const uint32_t arow = lane & 15;
    const uint32_t acol = (lane >> 4) * 8;
    uint32_t qh[4][4], ql[4][4];
    #pragma unroll
    for (int kc = 0; kc < 4; kc++) {
        uint32_t off = ((wid * 16 + arow) * SKS + kc * 16 + acol) * 2;
        ldsm_x4(qh[kc], sbase + off);
        ldsm_x4(ql[kc], sbase + 2 * APLANE * 2 + off);
    }

    // K/V gmem prefetch coords
    int krow[4], kcol[4];
    #pragma unroll
    for (int i = 0; i < 4; i++) {
        int s = tid + 256 * i;          // 1024 float4
        krow[i] = s >> 4;               // 0..63
        kcol[i] = (s & 15) * 4;
    }
    float4 rk[4], rv[4];
    #pragma unroll
    for (int i = 0; i < 4; i++) {
        const float* base = kv + (size_t)(krow[i] * 2 + b) * 2048 + n * 64 + kcol[i];
        rk[i] = *(const float4*)base;
        rv[i] = *(const float4*)(base + 1024);
    }

    const uint32_t brow = (lane & 7) + ((lane >> 4) & 1) * 8;
    const uint32_t bcol = ((lane >> 3) & 1) * 8;

    float acc_o[8][4] = {};
    float m0 = -1e30f, m1 = -1e30f, l0 = 0.f, l1 = 0.f;
    const float SC = 0.125f;

    for (int j0 = 0; j0 < SEQ; j0 += 64) {
        __syncthreads();    // previous readers done (incl. Q ldsm on iter 0)
        // store K (hi/lo) and V transposed (hi/lo)
        #pragma unroll
        for (int i = 0; i < 4; i++) {
            uint32_t hp[2], lp[2];
            split4(rk[i], hp, lp);
            int eo = (krow[i] * SKS + kcol[i]) >> 1;
            sm32[eo] = hp[0]; sm32[eo + 1] = hp[1];
            sm32[eo + (APLANE >> 1)] = lp[0]; sm32[eo + (APLANE >> 1) + 1] = lp[1];
            float vals[4] = {rv[i].x, rv[i].y, rv[i].z, rv[i].w};
            #pragma unroll
            for (int t = 0; t < 4; t++) {
                uint32_t u = __float_as_uint(vals[t]);
                float res = vals[t] - __uint_as_float(u & 0xffff0000u);
                __nv_bfloat16 lo = __float2bfloat16_rn(res);
                int idx = (kcol[i] + t) * SKS + krow[i];
                sm[2 * APLANE + idx] = (unsigned short)(u >> 16);
                sm[3 * APLANE + idx] = *(unsigned short*)&lo;
            }
        }
        __syncthreads();

        // issue next tile's LDGs early (latency hidden by compute)
        bool more = (j0 + 64 < SEQ);
        if (more) {
            #pragma unroll
            for (int i = 0; i < 4; i++) {
                const float* base = kv + (size_t)((j0 + 64 + krow[i]) * 2 + b) * 2048
                                    + n * 64 + kcol[i];
                rk[i] = *(const float4*)base;
                rv[i] = *(const float4*)(base + 1024);
            }
        }

        // ---- S = Q K^T (3x split) ----
        float s_acc[8][4] = {};
        #pragma unroll
        for (int kc = 0; kc < 4; kc++) {
            uint32_t bh[4][4], bl[4][4];
            #pragma unroll
            for (int np = 0; np < 4; np++) {
                uint32_t off = ((np * 16 + brow) * SKS + kc * 16 + bcol) * 2;
                ldsm_x4(bh[np], sbase + off);
                ldsm_x4(bl[np], sbase + APLANE * 2 + off);
            }
            #pragma unroll
            for (int nt = 0; nt < 8; nt++) {
                int p = nt >> 1, qd = (nt & 1) * 2;
                mma16816(s_acc[nt], qh[kc][0], qh[kc][1], qh[kc][2], qh[kc][3],
                         bh[p][qd], bh[p][qd + 1]);
                mma16816(s_acc[nt], qh[kc][0], qh[kc][1], qh[kc][2], qh[kc][3],
                         bl[p][qd], bl[p][qd + 1]);
                mma16816(s_acc[nt], ql[kc][0], ql[kc][1], ql[kc][2], ql[kc][3],
                         bh[p][qd], bh[p][qd + 1]);
            }
        }

        // ---- online softmax (rows r=lane>>2 and r+8) ----
        float vx0 = -1e30f, vx1 = -1e30f;
        #pragma unroll
        for (int nt = 0; nt < 8; nt++) {
            vx0 = fmaxf(vx0, fmaxf(s_acc[nt][0], s_acc[nt][1]));
            vx1 = fmaxf(vx1, fmaxf(s_acc[nt][2], s_acc[nt][3]));
        }
        vx0 *= SC; vx1 *= SC;
        #pragma unroll
        for (int off = 1; off <= 2; off <<= 1) {
            vx0 = fmaxf(vx0, __shfl_xor_sync(0xffffffffu, vx0, off));
            vx1 = fmaxf(vx1, __shfl_xor_sync(0xffffffffu, vx1, off));
        }
        float mn0 = fmaxf(m0, vx0), mn1 = fmaxf(m1, vx1);
        float al0 = __expf(m0 - mn0), al1 = __expf(m1 - mn1);
        float ls0 = 0.f, ls1 = 0.f;
        #pragma unroll
        for (int nt = 0; nt < 8; nt++) {
            float p0 = __expf(s_acc[nt][0] * SC - mn0);
            float p1 = __expf(s_acc[nt][1] * SC - mn0);
            float p2 = __expf(s_acc[nt][2] * SC - mn1);
            float p3 = __expf(s_acc[nt][3] * SC - mn1);
            ls0 += p0 + p1; ls1 += p2 + p3;
            s_acc[nt][0] = p0; s_acc[nt][1] = p1;
            s_acc[nt][2] = p2; s_acc[nt][3] = p3;
        }
        #pragma unroll
        for (int off = 1; off <= 2; off <<= 1) {
            ls0 += __shfl_xor_sync(0xffffffffu, ls0, off);
            ls1 += __shfl_xor_sync(0xffffffffu, ls1, off);
        }
        l0 = l0 * al0 + ls0; l1 = l1 * al1 + ls1;
        m0 = mn0; m1 = mn1;
        #pragma unroll
        for (int nt = 0; nt < 8; nt++) {
            acc_o[nt][0] *= al0; acc_o[nt][1] *= al0;
            acc_o[nt][2] *= al1; acc_o[nt][3] *= al1;
        }

        // ---- pack P fragments (A operand for PV) ----
        uint32_t pah[4][4], pal[4][4];
        #pragma unroll
        for (int kc = 0; kc < 4; kc++) {
            pah[kc][0] = pack_hi2(s_acc[2*kc][0],   s_acc[2*kc][1]);
            pah[kc][1] = pack_hi2(s_acc[2*kc][2],   s_acc[2*kc][3]);
            pah[kc][2] = pack_hi2(s_acc[2*kc+1][0], s_acc[2*kc+1][1]);
            pah[kc][3] = pack_hi2(s_acc[2*kc+1][2], s_acc[2*kc+1][3]);
            pal[kc][0] = pack_lo2(s_acc[2*kc][0],   s_acc[2*kc][1]);
            pal[kc][1] = pack_lo2(s_acc[2*kc][2],   s_acc[2*kc][3]);
            pal[kc][2] = pack_lo2(s_acc[2*kc+1][0], s_acc[2*kc+1][1]);
            pal[kc][3] = pack_lo2(s_acc[2*kc+1][2], s_acc[2*kc+1][3]);
        }

        // ---- O += P V (3x split), V transposed in smem ----
        #pragma unroll
        for (int kc = 0; kc < 4; kc++) {
            uint32_t vh[4][4], vl[4][4];
            #pragma unroll
            for (int np = 0; np < 4; np++) {
                uint32_t off = (2 * APLANE + (np * 16 + brow) * SKS + kc * 16 + bcol) * 2;
                ldsm_x4(vh[np], sbase + off);
                ldsm_x4(vl[np], sbase + APLANE * 2 + off);
            }
            #pragma unroll
            for (int nt = 0; nt < 8; nt++) {
                int p = nt >> 1, qd = (nt & 1) * 2;
                mma16816(acc_o[nt], pah[kc][0], pah[kc][1], pah[kc][2], pah[kc][3],
                         vh[p][qd], vh[p][qd + 1]);
                mma16816(acc_o[nt], pah[kc][0], pah[kc][1], pah[kc][2], pah[kc][3],
                         vl[p][qd], vl[p][qd + 1]);
                mma16816(acc_o[nt], pal[kc][0], pal[kc][1], pal[kc][2], pal[kc][3],
                         vh[p][qd], vh[p][qd + 1]);
            }
        }
    }

    // ---- epilogue: O / l -> vec ----
    float inv0 = 1.f / l0, inv1 = 1.f / l1;
    int row0 = i0 + wid * 16 + (lane >> 2);
    int col  = n * 64 + (lane & 3) * 2;
    #pragma unroll
    for (int nt = 0; nt < 8; nt++) {
        float2 r0 = make_float2(acc_o[nt][0] * inv0, acc_o[nt][1] * inv0);
        float2 r1 = make_float2(acc_o[nt][2] * inv1, acc_o[nt][3] * inv1);
        size_t o0 = (size_t)(row0 * 2 + b) * 1024 + col + nt * 8;
        size_t o1 = (size_t)((row0 + 8) * 2 + b) * 1024 + col + nt * 8;
        *(float2*)&vec[o0] = r0;
        *(float2*)&vec[o1] = r1;
    }
}

// ================= LayerNorm kernels ======================================
__device__ __forceinline__ void block_stats(float4 v, int t, float& mean, float& rstd)
{
    __shared__ float as[8], aq[8];
    float s  = v.x + v.y + v.z + v.w;
    float ss = v.x*v.x + v.y*v.y + v.z*v.z + v.w*v.w;
    #pragma unroll
    for (int off = 16; off; off >>= 1) {
        s  += __shfl_xor_sync(0xffffffffu, s, off);
        ss += __shfl_xor_sync(0xffffffffu, ss, off);
    }
    if ((t & 31) == 0) { as[t >> 5] = s; aq[t >> 5] = ss; }
    __syncthreads();
    s = 0.f; ss = 0.f;
    #pragma unroll
    for (int w = 0; w < 8; w++) { s += as[w]; ss += aq[w]; }
    mean = s * (1.f / 1024.f);
    float var = ss * (1.f / 1024.f) - mean * mean;
    rstd = rsqrtf(var + 1e-5f);
}

__global__ void __launch_bounds__(256) ln_kernel(
    const float* __restrict__ x, const float* __restrict__ g,
    const float* __restrict__ bt, float* __restrict__ y)
{
    int row = blockIdx.x;
    int t = threadIdx.x;
    float4 v = *(const float4*)&x[(size_t)row * 1024 + t * 4];
    float mean, rstd;
    block_stats(v, t, mean, rstd);
    float4 gv = *(const float4*)&g[t * 4];
    float4 bv = *(const float4*)&bt[t * 4];
    float4 o;
    o.x = (v.x - mean) * rstd * gv.x + bv.x;
    o.y = (v.y - mean) * rstd * gv.y + bv.y;
    o.z = (v.z - mean) * rstd * gv.z + bv.z;
    o.w = (v.w - mean) * rstd * gv.w + bv.w;
    *(float4*)&y[(size_t)row * 1024 + t * 4] = o;
}

__global__ void __launch_bounds__(256) ln_final_kernel(
    const float* __restrict__ x, const float* __restrict__ g,
    const float* __restrict__ bt, float* __restrict__ y)
{
    int row = blockIdx.x;
    int t = threadIdx.x;
    float4 v = *(const float4*)&x[(size_t)row * 1024 + t * 4];
    float mean, rstd;
    block_stats(v, t, mean, rstd);
    float4 gv = *(const float4*)&g[t * 4];
    float4 bv = *(const float4*)&bt[t * 4];
    float ln[4] = {
        (v.x - mean) * rstd * gv.x + bv.x,
        (v.y - mean) * rstd * gv.y + bv.y,
        (v.z - mean) * rstd * gv.z + bv.z,
        (v.w - mean) * rstd * gv.w + bv.w
    };
    float bcol = (float)(row & 1);
    float o4[4];
    #pragma unroll
    for (int j = 0; j < 4; j++) {
        int d = t * 4 + j;
        float e = (float)(d & ~1) * (1.f / 1024.f);
        float freq = __expf(-9.210340371976184f * e);  // ln(10000)
        float ang = bcol * freq;
        float pe = (d & 1) ? cosf(ang) : sinf(ang);
        o4[j] = 2.f * ln[j] + pe;
    }
    float4 o; o.x = o4[0]; o.y = o4[1]; o.z = o4[2]; o.w = o4[3];
    *(float4*)&y[(size_t)row * 1024 + t * 4] = o;
}

// ================= launch ==================================================
extern "C" void kernel_launch(void* const* d_in, const int* in_sizes, int n_in,
                              void* d_out, int out_size)
{
    const float* dec = (const float*)d_in[0];
    const float* Wq  = (const float*)d_in[1];
    const float* Wkv = (const float*)d_in[2];
    const float* Wo  = (const float*)d_in[3];
    const float* g1  = (const float*)d_in[4];
    const float* b1  = (const float*)d_in[5];
    const float* Wff = (const float*)d_in[6];
    const float* g2  = (const float*)d_in[7];
    const float* b2  = (const float*)d_in[8];
    float* out = (float*)d_out;

    float *q, *kv, *vec, *h0, *h1, *f0;
    cudaGetSymbolAddress((void**)&q,   g_q);
    cudaGetSymbolAddress((void**)&kv,  g_kv);
    cudaGetSymbolAddress((void**)&vec, g_vec);
    cudaGetSymbolAddress((void**)&h0,  g_h0);
    cudaGetSymbolAddress((void**)&h1,  g_h1);
    cudaGetSymbolAddress((void**)&f0,  g_f0);

    cudaFuncSetAttribute(gemm_bf3<false>,
                         cudaFuncAttributeMaxDynamicSharedMemorySize, GSMEM_BYTES);
    cudaFuncSetAttribute(gemm_bf3<true>,
                         cudaFuncAttributeMaxDynamicSharedMemorySize, GSMEM_BYTES);

    // q = dec @ Wq^T   [4096,1024]
    gemm_bf3<false><<<dim3(1024/128, 4096/128), 256, GSMEM_BYTES>>>(
        dec, Wq, nullptr, q, MTOK, 1024, 1024);
    // kv = dec @ Wkv^T [4096,2048]
    gemm_bf3<false><<<dim3(2048/128, 4096/128), 256, GSMEM_BYTES>>>(
        dec, Wkv, nullptr, kv, MTOK, 2048, 1024);
    // attention -> vec [4096,1024]
    attn_tc<<<dim3(SEQ/128, BATCH, NH), 256>>>(q, kv, vec);
    // h0 = dec + vec @ Wo^T
    gemm_bf3<true><<<dim3(1024/128, 4096/128), 256, GSMEM_BYTES>>>(
        vec, Wo, dec, h0, MTOK, 1024, 1024);
    // h1 = LN(h0)
    ln_kernel<<<MTOK, 256>>>(h0, g1, b1, h1);
    // f0 = h1 + h1 @ Wff^T
    gemm_bf3<true><<<dim3(1024/128, 4096/128), 256, GSMEM_BYTES>>>(
        h1, Wff, h1, f0, MTOK, 1024, 1024);
    // out = 2*LN(f0) + pe[b]
    ln_final_kernel<<<MTOK, 256>>>(f0, g2, b2, out);
}

// round 4
// speedup vs baseline: 2.5712x; 1.1383x over previous
#include <cuda_runtime.h>
#include <cuda_bf16.h>
#include <cstdint>

// Problem constants
#define SEQ   2048
#define BATCH 2
#define DM    1024
#define NH    16
#define DH    64
#define MTOK  (SEQ*BATCH)   // 4096 token rows

// ---------------- scratch (device globals) --------------------------------
// bf16 hi/lo planes
__device__ __nv_bfloat16 g_dh [MTOK * DM],      g_dl [MTOK * DM];
__device__ __nv_bfloat16 g_wqh[DM * DM],        g_wql[DM * DM];
__device__ __nv_bfloat16 g_wkvh[2 * DM * DM],   g_wkvl[2 * DM * DM];
__device__ __nv_bfloat16 g_woh[DM * DM],        g_wol[DM * DM];
__device__ __nv_bfloat16 g_wffh[DM * DM],       g_wffl[DM * DM];
__device__ __nv_bfloat16 g_qh [MTOK * DM],      g_ql [MTOK * DM];
__device__ __nv_bfloat16 g_kh [MTOK * DM],      g_kl [MTOK * DM];
__device__ __nv_bfloat16 g_vth[BATCH*NH*DH*SEQ], g_vtl[BATCH*NH*DH*SEQ]; // [b,n][d][j]
__device__ __nv_bfloat16 g_vech[MTOK * DM],     g_vecl[MTOK * DM];
__device__ __nv_bfloat16 g_h1h[MTOK * DM],      g_h1l[MTOK * DM];
// fp32
__device__ float g_h0[MTOK * DM];
__device__ float g_f0[MTOK * DM];

// ===================== common helpers ======================================
__device__ __forceinline__ void ldsm_x4(uint32_t r[4], uint32_t addr) {
    asm volatile("ldmatrix.sync.aligned.m8n8.x4.shared.b16 {%0,%1,%2,%3}, [%4];\n"
                 : "=r"(r[0]), "=r"(r[1]), "=r"(r[2]), "=r"(r[3]) : "r"(addr));
}

__device__ __forceinline__ void mma16816(float c[4],
                                         uint32_t a0, uint32_t a1, uint32_t a2, uint32_t a3,
                                         uint32_t b0, uint32_t b1) {
    asm volatile(
        "mma.sync.aligned.m16n8k16.row.col.f32.bf16.bf16.f32 "
        "{%0,%1,%2,%3}, {%4,%5,%6,%7}, {%8,%9}, {%0,%1,%2,%3};\n"
        : "+f"(c[0]), "+f"(c[1]), "+f"(c[2]), "+f"(c[3])
        : "r"(a0), "r"(a1), "r"(a2), "r"(a3), "r"(b0), "r"(b1));
}

__device__ __forceinline__ void cp16(uint32_t dst, const void* src) {
    asm volatile("cp.async.cg.shared.global [%0], [%1], 16;\n" :: "r"(dst), "l"(src));
}
#define CP_COMMIT()  asm volatile("cp.async.commit_group;\n")
#define CP_WAIT(n)   asm volatile("cp.async.wait_group %0;\n" :: "n"(n))

__device__ __forceinline__ void split4(float4 v, uint32_t hp[2], uint32_t lp[2]) {
    uint32_t u0 = __float_as_uint(v.x), u1 = __float_as_uint(v.y);
    uint32_t u2 = __float_as_uint(v.z), u3 = __float_as_uint(v.w);
    hp[0] = __byte_perm(u0, u1, 0x7632);
    hp[1] = __byte_perm(u2, u3, 0x7632);
    float r0 = v.x - __uint_as_float(u0 & 0xffff0000u);
    float r1 = v.y - __uint_as_float(u1 & 0xffff0000u);
    float r2 = v.z - __uint_as_float(u2 & 0xffff0000u);
    float r3 = v.w - __uint_as_float(u3 & 0xffff0000u);
    __nv_bfloat162 l01 = __floats2bfloat162_rn(r0, r1);
    __nv_bfloat162 l23 = __floats2bfloat162_rn(r2, r3);
    lp[0] = *(uint32_t*)&l01;
    lp[1] = *(uint32_t*)&l23;
}

__device__ __forceinline__ uint32_t pack_hi2(float a, float b) {
    return __byte_perm(__float_as_uint(a), __float_as_uint(b), 0x7632);
}
__device__ __forceinline__ uint32_t pack_lo2(float a, float b) {
    float ra = a - __uint_as_float(__float_as_uint(a) & 0xffff0000u);
    float rb = b - __uint_as_float(__float_as_uint(b) & 0xffff0000u);
    __nv_bfloat162 l = __floats2bfloat162_rn(ra, rb);
    return *(uint32_t*)&l;
}
__device__ __forceinline__ unsigned short hi16(float x) {
    return (unsigned short)(__float_as_uint(x) >> 16);
}
__device__ __forceinline__ unsigned short lo16(float x) {
    float r = x - __uint_as_float(__float_as_uint(x) & 0xffff0000u);
    __nv_bfloat16 b = __float2bfloat16_rn(r);
    return *(unsigned short*)&b;
}

// ================= fp32 -> hi/lo plane conversion =========================
__global__ void __launch_bounds__(256) conv_split(
    const float* __restrict__ x, __nv_bfloat16* __restrict__ h,
    __nv_bfloat16* __restrict__ l, int n4)
{
    int i = blockIdx.x * 256 + threadIdx.x;
    if (i >= n4) return;
    float4 v = ((const float4*)x)[i];
    uint32_t hp[2], lp[2];
    split4(v, hp, lp);
    ((uint2*)h)[i] = make_uint2(hp[0], hp[1]);
    ((uint2*)l)[i] = make_uint2(lp[0], lp[1]);
}

// ===================== bf16-plane GEMM (split-3x, cp.async) ================
// C[M,N] = (Ah+Al)[M,K] * (Bh+Bl)[N,K]^T via hh+hl+lh.
// MODE 0: Cf = acc + AddF (fp32)
// MODE 1: Cf = acc + (AddH+AddL)
// MODE 2: Ch/Cl planes [M,N]
// MODE 3: kv special: cols<1024 -> K planes [token][1024]; else V^T scatter.
#define GP_STRIDE 40
#define GP_BYTES  10240                  // 128 rows * 80B
#define GSTAGE_BYTES (4 * GP_BYTES)      // Ahi,Alo,Bhi,Blo
#define GSMEM_BYTES (2 * GSTAGE_BYTES)   // 81920

template<int MODE>
__global__ void __launch_bounds__(256, 2) gemm_bf16(
    const __nv_bfloat16* __restrict__ Ah, const __nv_bfloat16* __restrict__ Al,
    const __nv_bfloat16* __restrict__ Bh, const __nv_bfloat16* __restrict__ Bl,
    const float* __restrict__ AddF,
    const __nv_bfloat16* __restrict__ AddH, const __nv_bfloat16* __restrict__ AddL,
    float* __restrict__ Cf,
    __nv_bfloat16* __restrict__ Ch, __nv_bfloat16* __restrict__ Cl,
    __nv_bfloat16* __restrict__ Vth, __nv_bfloat16* __restrict__ Vtl,
    int M, int N, int K)
{
    extern __shared__ __align__(16) unsigned char smraw[];
    uint32_t sbase = (uint32_t)__cvta_generic_to_shared(smraw);

    const int tid  = threadIdx.x;
    const int lane = tid & 31;
    const int wid  = tid >> 5;
    const int wm   = wid >> 2;
    const int wn   = wid & 3;
    const int bm   = blockIdx.y * 128;
    const int bn   = blockIdx.x * 128;

    // per-thread cp.async plane assignment: plane = tid>>6 (64 threads/plane)
    const int plane = tid >> 6;
    const __nv_bfloat16* srcbase =
        (plane == 0) ? Ah + (size_t)bm * K :
        (plane == 1) ? Al + (size_t)bm * K :
        (plane == 2) ? Bh + (size_t)bn * K :
                       Bl + (size_t)bn * K;

    auto issue = [&](int k0, int buf) {
        uint32_t dbase = sbase + buf * GSTAGE_BYTES + plane * GP_BYTES;
        #pragma unroll
        for (int i = 0; i < 8; i++) {
            int chunk = (tid & 63) + 64 * i;   // 0..511
            int row = chunk >> 2, c = chunk & 3;
            cp16(dbase + row * 80 + c * 16,
                 srcbase + (size_t)row * K + k0 + c * 8);
        }
        CP_COMMIT();
    };

    float acc[4][4][4] = {};

    const uint32_t arow = lane & 15;
    const uint32_t acol = ((lane >> 4) & 1) * 8;
    const uint32_t brow = (lane & 7) + ((lane >> 4) & 1) * 8;
    const uint32_t bcol = ((lane >> 3) & 1) * 8;

    auto compute = [&](int buf) {
        uint32_t base = sbase + buf * GSTAGE_BYTES;
        #pragma unroll
        for (int s = 0; s < 2; s++) {
            uint32_t ah[4][4], al[4][4], bh[2][4], bl[2][4];
            #pragma unroll
            for (int mt = 0; mt < 4; mt++) {
                uint32_t off = (((wm * 64 + mt * 16 + arow) * GP_STRIDE) + acol + s * 16) << 1;
                ldsm_x4(ah[mt], base + off);
                ldsm_x4(al[mt], base + GP_BYTES + off);
            }
            #pragma unroll
            for (int np = 0; np < 2; np++) {
                uint32_t off = (((wn * 32 + np * 16 + brow) * GP_STRIDE) + bcol + s * 16) << 1;
                ldsm_x4(bh[np], base + 2 * GP_BYTES + off);
                ldsm_x4(bl[np], base + 3 * GP_BYTES + off);
            }
            #pragma unroll
            for (int mt = 0; mt < 4; mt++)
                #pragma unroll
                for (int nt = 0; nt < 4; nt++) {
                    int p = nt >> 1, q = (nt & 1) * 2;
                    mma16816(acc[mt][nt], ah[mt][0], ah[mt][1], ah[mt][2], ah[mt][3],
                             bh[p][q], bh[p][q + 1]);
                    mma16816(acc[mt][nt], ah[mt][0], ah[mt][1], ah[mt][2], ah[mt][3],
                             bl[p][q], bl[p][q + 1]);
                    mma16816(acc[mt][nt], al[mt][0], al[mt][1], al[mt][2], al[mt][3],
                             bh[p][q], bh[p][q + 1]);
                }
        }
    };

    issue(0, 0);
    issue(32, 1);
    CP_WAIT(1);
    __syncthreads();

    for (int k0 = 0; k0 < K; k0 += 32) {
        int buf = (k0 >> 5) & 1;
        compute(buf);
        __syncthreads();
        if (k0 + 64 < K) issue(k0 + 64, buf);
        if (k0 + 32 < K) { CP_WAIT(1); __syncthreads(); }
    }

    // epilogue
    #pragma unroll
    for (int mt = 0; mt < 4; mt++) {
        #pragma unroll
        for (int nt = 0; nt < 4; nt++) {
            int r0 = bm + wm * 64 + mt * 16 + (lane >> 2);
            int c  = bn + wn * 32 + nt * 8 + (lane & 3) * 2;
            float a0 = acc[mt][nt][0], a1 = acc[mt][nt][1];
            float a2 = acc[mt][nt][2], a3 = acc[mt][nt][3];
            if constexpr (MODE == 0) {
                size_t o0 = (size_t)r0 * N + c, o1 = (size_t)(r0 + 8) * N + c;
                float2 x0 = *(const float2*)&AddF[o0];
                float2 x1 = *(const float2*)&AddF[o1];
                *(float2*)&Cf[o0] = make_float2(a0 + x0.x, a1 + x0.y);
                *(float2*)&Cf[o1] = make_float2(a2 + x1.x, a3 + x1.y);
            } else if constexpr (MODE == 1) {
                size_t o0 = (size_t)r0 * N + c, o1 = (size_t)(r0 + 8) * N + c;
                __nv_bfloat162 h0v = *(const __nv_bfloat162*)&AddH[o0];
                __nv_bfloat162 l0v = *(const __nv_bfloat162*)&AddL[o0];
                __nv_bfloat162 h1v = *(const __nv_bfloat162*)&AddH[o1];
                __nv_bfloat162 l1v = *(const __nv_bfloat162*)&AddL[o1];
                a0 += __bfloat162float(h0v.x) + __bfloat162float(l0v.x);
                a1 += __bfloat162float(h0v.y) + __bfloat162float(l0v.y);
                a2 += __bfloat162float(h1v.x) + __bfloat162float(l1v.x);
                a3 += __bfloat162float(h1v.y) + __bfloat162float(l1v.y);
                *(float2*)&Cf[o0] = make_float2(a0, a1);
                *(float2*)&Cf[o1] = make_float2(a2, a3);
            } else if constexpr (MODE == 2) {
                size_t o0 = (size_t)r0 * N + c, o1 = (size_t)(r0 + 8) * N + c;
                ((uint32_t*)Ch)[o0 >> 1] = pack_hi2(a0, a1);
                ((uint32_t*)Cl)[o0 >> 1] = pack_lo2(a0, a1);
                ((uint32_t*)Ch)[o1 >> 1] = pack_hi2(a2, a3);
                ((uint32_t*)Cl)[o1 >> 1] = pack_lo2(a2, a3);
            } else {  // MODE 3: kv
                if (c < 1024) {
                    size_t o0 = (size_t)r0 * 1024 + c, o1 = (size_t)(r0 + 8) * 1024 + c;
                    ((uint32_t*)Ch)[o0 >> 1] = pack_hi2(a0, a1);
                    ((uint32_t*)Cl)[o0 >> 1] = pack_lo2(a0, a1);
                    ((uint32_t*)Ch)[o1 >> 1] = pack_hi2(a2, a3);
                    ((uint32_t*)Cl)[o1 >> 1] = pack_lo2(a2, a3);
                } else {
                    int e = c - 1024, nn = e >> 6, dd = e & 63;
                    int b0 = r0 & 1, j0 = r0 >> 1;
                    size_t base = ((size_t)(b0 * 16 + nn) * 64 + dd) * 2048;
                    unsigned short* VH = (unsigned short*)Vth;
                    unsigned short* VL = (unsigned short*)Vtl;
                    VH[base + j0]            = hi16(a0);
                    VH[base + 2048 + j0]     = hi16(a1);
                    VH[base + j0 + 4]        = hi16(a2);
                    VH[base + 2048 + j0 + 4] = hi16(a3);
                    VL[base + j0]            = lo16(a0);
                    VL[base + 2048 + j0]     = lo16(a1);
                    VL[base + j0 + 4]        = lo16(a2);
                    VL[base + 2048 + j0 + 4] = lo16(a3);
                }
            }
        }
    }
}

// ================= Tensor-core flash attention (bf16 planes, cp.async) ====
// Block: 128 q-rows of one (b,n). smem: Qh|Ql [128][72] + 2 stages of
// (Kh|Kl|Vh|Vl)[64][72]. V comes pre-transposed from kv GEMM.
#define AP 72                 // pitch (elems): 144B rows, 16B-aligned, ldsm-safe
#define QPLANE (128 * AP)     // 9216
#define KPLANE (64 * AP)      // 4608
#define ASTAGE (4 * KPLANE)   // 18432 elems
#define ASMEM_ELEMS (2 * QPLANE + 2 * ASTAGE)
#define ASMEM_BYTES (ASMEM_ELEMS * 2)   // 110592

__global__ void __launch_bounds__(256) attn_tc(
    const __nv_bfloat16* __restrict__ qh, const __nv_bfloat16* __restrict__ ql,
    const __nv_bfloat16* __restrict__ kh, const __nv_bfloat16* __restrict__ kl,
    const __nv_bfloat16* __restrict__ vth, const __nv_bfloat16* __restrict__ vtl,
    __nv_bfloat16* __restrict__ vech, __nv_bfloat16* __restrict__ vecl)
{
    extern __shared__ __align__(16) unsigned char smraw[];
    uint32_t sbase = (uint32_t)__cvta_generic_to_shared(smraw);

    const int tid  = threadIdx.x;
    const int lane = tid & 31;
    const int wid  = tid >> 5;
    const int i0   = blockIdx.x * 128;
    const int b    = blockIdx.y;
    const int n    = blockIdx.z;

    // Q staging: 2 planes x 128 rows x 8 chunks; plane = tid>>7
    {
        int qp = tid >> 7;
        const __nv_bfloat16* src0 = (qp ? ql : qh) + (size_t)b * 1024 + n * 64;
        uint32_t dbase = sbase + qp * QPLANE * 2;
        #pragma unroll
        for (int i = 0; i < 8; i++) {
            int chunk = (tid & 127) + 128 * i;   // 0..1023
            int row = chunk >> 3, c = chunk & 7;
            cp16(dbase + row * 144 + c * 16,
                 src0 + (size_t)(i0 + row) * 2048 + c * 8);
        }
    }

    // K/V staging: plane = tid>>6
    const int plane = tid >> 6;
    const __nv_bfloat16* kvsrc =
        (plane == 0) ? kh + (size_t)b * 1024 + n * 64 :
        (plane == 1) ? kl + (size_t)b * 1024 + n * 64 :
        (plane == 2) ? vth + (size_t)(b * 16 + n) * 64 * 2048 :
                       vtl + (size_t)(b * 16 + n) * 64 * 2048;
    const size_t kvpitch = (plane < 2) ? 2048 : 2048;  // token stride / d stride
    const bool isK = (plane < 2);

    auto issue_kv = [&](int j0, int buf) {
        uint32_t dbase = sbase + (2 * QPLANE + buf * ASTAGE + plane * KPLANE) * 2;
        #pragma unroll
        for (int i = 0; i < 8; i++) {
            int chunk = (tid & 63) + 64 * i;     // 0..511
            int row = chunk >> 3, c = chunk & 7;
            const __nv_bfloat16* s = isK
                ? kvsrc + (size_t)(j0 + row) * kvpitch + c * 8
                : kvsrc + (size_t)row * kvpitch + j0 + c * 8;
            cp16(dbase + row * 144 + c * 16, s);
        }
        CP_COMMIT();
    };

    issue_kv(0, 0);     // commits group containing Q + stage0
    issue_kv(64, 1);
    CP_WAIT(1);
    __syncthreads();

    // Q fragments
    const uint32_t arow = lane & 15;
    const uint32_t acol = (lane >> 4) * 8;
    uint32_t qfh[4][4], qfl[4][4];
    #pragma unroll
    for (int kc = 0; kc < 4; kc++) {
        uint32_t off = ((wid * 16 + arow) * AP + kc * 16 + acol) * 2;
        ldsm_x4(qfh[kc], sbase + off);
        ldsm_x4(qfl[kc], sbase + QPLANE * 2 + off);
    }

    const uint32_t brow = (lane & 7) + ((lane >> 4) & 1) * 8;
    const uint32_t bcol = ((lane >> 3) & 1) * 8;

    float acc_o[8][4] = {};
    float m0 = -1e30f, m1 = -1e30f, l0 = 0.f, l1 = 0.f;
    const float SC = 0.125f;

    for (int j0 = 0; j0 < SEQ; j0 += 64) {
        int buf = (j0 >> 6) & 1;
        uint32_t stg = sbase + (2 * QPLANE + buf * ASTAGE) * 2;

        // ---- S = Q K^T ----
        float s_acc[8][4] = {};
        #pragma unroll
        for (int kc = 0; kc < 4; kc++) {
            uint32_t bh[4][4], blr[4][4];
            #pragma unroll
            for (int np = 0; np < 4; np++) {
                uint32_t off = ((np * 16 + brow) * AP + kc * 16 + bcol) * 2;
                ldsm_x4(bh[np],  stg + off);
                ldsm_x4(blr[np], stg + KPLANE * 2 + off);
            }
            #pragma unroll
            for (int nt = 0; nt < 8; nt++) {
                int p = nt >> 1, qd = (nt & 1) * 2;
                mma16816(s_acc[nt], qfh[kc][0], qfh[kc][1], qfh[kc][2], qfh[kc][3],
                         bh[p][qd], bh[p][qd + 1]);
                mma16816(s_acc[nt], qfh[kc][0], qfh[kc][1], qfh[kc][2], qfh[kc][3],
                         blr[p][qd], blr[p][qd + 1]);
                mma16816(s_acc[nt], qfl[kc][0], qfl[kc][1], qfl[kc][2], qfl[kc][3],
                         bh[p][qd], bh[p][qd + 1]);
            }
        }

        // ---- online softmax ----
        float vx0 = -1e30f, vx1 = -1e30f;
        #pragma unroll
        for (int nt = 0; nt < 8; nt++) {
            vx0 = fmaxf(vx0, fmaxf(s_acc[nt][0], s_acc[nt][1]));
            vx1 = fmaxf(vx1, fmaxf(s_acc[nt][2], s_acc[nt][3]));
        }
        vx0 *= SC; vx1 *= SC;
        #pragma unroll
        for (int off = 1; off <= 2; off <<= 1) {
            vx0 = fmaxf(vx0, __shfl_xor_sync(0xffffffffu, vx0, off));
            vx1 = fmaxf(vx1, __shfl_xor_sync(0xffffffffu, vx1, off));
        }
        float mn0 = fmaxf(m0, vx0), mn1 = fmaxf(m1, vx1);
        float al0 = __expf(m0 - mn0), al1 = __expf(m1 - mn1);
        float ls0 = 0.f, ls1 = 0.f;
        #pragma unroll
        for (int nt = 0; nt < 8; nt++) {
            float p0 = __expf(s_acc[nt][0] * SC - mn0);
            float p1 = __expf(s_acc[nt][1] * SC - mn0);
            float p2 = __expf(s_acc[nt][2] * SC - mn1);
            float p3 = __expf(s_acc[nt][3] * SC - mn1);
            ls0 += p0 + p1; ls1 += p2 + p3;
            s_acc[nt][0] = p0; s_acc[nt][1] = p1;
            s_acc[nt][2] = p2; s_acc[nt][3] = p3;
        }
        #pragma unroll
        for (int off = 1; off <= 2; off <<= 1) {
            ls0 += __shfl_xor_sync(0xffffffffu, ls0, off);
            ls1 += __shfl_xor_sync(0xffffffffu, ls1, off);
        }
        l0 = l0 * al0 + ls0; l1 = l1 * al1 + ls1;
        m0 = mn0; m1 = mn1;
        #pragma unroll
        for (int nt = 0; nt < 8; nt++) {
            acc_o[nt][0] *= al0; acc_o[nt][1] *= al0;
            acc_o[nt][2] *= al1; acc_o[nt][3] *= al1;
        }

        // ---- pack P fragments ----
        uint32_t pah[4][4], pal[4][4];
        #pragma unroll
        for (int kc = 0; kc < 4; kc++) {
            pah[kc][0] = pack_hi2(s_acc[2*kc][0],   s_acc[2*kc][1]);
            pah[kc][1] = pack_hi2(s_acc[2*kc][2],   s_acc[2*kc][3]);
            pah[kc][2] = pack_hi2(s_acc[2*kc+1][0], s_acc[2*kc+1][1]);
            pah[kc][3] = pack_hi2(s_acc[2*kc+1][2], s_acc[2*kc+1][3]);
            pal[kc][0] = pack_lo2(s_acc[2*kc][0],   s_acc[2*kc][1]);
            pal[kc][1] = pack_lo2(s_acc[2*kc][2],   s_acc[2*kc][3]);
            pal[kc][2] = pack_lo2(s_acc[2*kc+1][0], s_acc[2*kc+1][1]);
            pal[kc][3] = pack_lo2(s_acc[2*kc+1][2], s_acc[2*kc+1][3]);
        }

        // ---- O += P V ----
        #pragma unroll
        for (int kc = 0; kc < 4; kc++) {
            uint32_t vh[4][4], vl[4][4];
            #pragma unroll
            for (int np = 0; np < 4; np++) {
                uint32_t off = ((np * 16 + brow) * AP + kc * 16 + bcol) * 2;
                ldsm_x4(vh[np], stg + 2 * KPLANE * 2 + off);
                ldsm_x4(vl[np], stg + 3 * KPLANE * 2 + off);
            }
            #pragma unroll
            for (int nt = 0; nt < 8; nt++) {
                int p = nt >> 1, qd = (nt & 1) * 2;
                mma16816(acc_o[nt], pah[kc][0], pah[kc][1], pah[kc][2], pah[kc][3],
                         vh[p][qd], vh[p][qd + 1]);
                mma16816(acc_o[nt], pah[kc][0], pah[kc][1], pah[kc][2], pah[kc][3],
                         vl[p][qd], vl[p][qd + 1]);
                mma16816(acc_o[nt], pal[kc][0], pal[kc][1], pal[kc][2], pal[kc][3],
                         vh[p][qd], vh[p][qd + 1]);
            }
        }

        __syncthreads();                       // readers done with buf
        if (j0 + 128 < SEQ) issue_kv(j0 + 128, buf);
        if (j0 + 64 < SEQ) { CP_WAIT(1); __syncthreads(); }
    }

    // ---- epilogue: write vec hi/lo planes ----
    float inv0 = 1.f / l0, inv1 = 1.f / l1;
    int row0 = i0 + wid * 16 + (lane >> 2);
    int colb = n * 64 + (lane & 3) * 2;
    #pragma unroll
    for (int nt = 0; nt < 8; nt++) {
        float a0 = acc_o[nt][0] * inv0, a1 = acc_o[nt][1] * inv0;
        float a2 = acc_o[nt][2] * inv1, a3 = acc_o[nt][3] * inv1;
        size_t o0 = ((size_t)row0 * 2 + b) * 1024 + colb + nt * 8;
        size_t o1 = ((size_t)(row0 + 8) * 2 + b) * 1024 + colb + nt * 8;
        ((uint32_t*)vech)[o0 >> 1] = pack_hi2(a0, a1);
        ((uint32_t*)vecl)[o0 >> 1] = pack_lo2(a0, a1);
        ((uint32_t*)vech)[o1 >> 1] = pack_hi2(a2, a3);
        ((uint32_t*)vecl)[o1 >> 1] = pack_lo2(a2, a3);
    }
}

// ================= LayerNorm kernels ======================================
__device__ __forceinline__ void block_stats(float4 v, int t, float& mean, float& rstd)
{
    __shared__ float as[8], aq[8];
    float s  = v.x + v.y + v.z + v.w;
    float ss = v.x*v.x + v.y*v.y + v.z*v.z + v.w*v.w;
    #pragma unroll
    for (int off = 16; off; off >>= 1) {
        s  += __shfl_xor_sync(0xffffffffu, s, off);
        ss += __shfl_xor_sync(0xffffffffu, ss, off);
    }
    if ((t & 31) == 0) { as[t >> 5] = s; aq[t >> 5] = ss; }
    __syncthreads();
    s = 0.f; ss = 0.f;
    #pragma unroll
    for (int w = 0; w < 8; w++) { s += as[w]; ss += aq[w]; }
    mean = s * (1.f / 1024.f);
    float var = ss * (1.f / 1024.f) - mean * mean;
    rstd = rsqrtf(var + 1e-5f);
}

// LN1: fp32 in -> hi/lo bf16 planes out
__global__ void __launch_bounds__(256) ln_kernel(
    const float* __restrict__ x, const float* __restrict__ g,
    const float* __restrict__ bt, __nv_bfloat16* __restrict__ yh,
    __nv_bfloat16* __restrict__ yl)
{
    int row = blockIdx.x;
    int t = threadIdx.x;
    float4 v = *(const float4*)&x[(size_t)row * 1024 + t * 4];
    float mean, rstd;
    block_stats(v, t, mean, rstd);
    float4 gv = *(const float4*)&g[t * 4];
    float4 bv = *(const float4*)&bt[t * 4];
    float o0 = (v.x - mean) * rstd * gv.x + bv.x;
    float o1 = (v.y - mean) * rstd * gv.y + bv.y;
    float o2 = (v.z - mean) * rstd * gv.z + bv.z;
    float o3 = (v.w - mean) * rstd * gv.w + bv.w;
    size_t idx = ((size_t)row * 1024 + t * 4) >> 1;    // u32 index
    ((uint2*)yh)[idx >> 1] = make_uint2(pack_hi2(o0, o1), pack_hi2(o2, o3));
    ((uint2*)yl)[idx >> 1] = make_uint2(pack_lo2(o0, o1), pack_lo2(o2, o3));
}

__global__ void __launch_bounds__(256) ln_final_kernel(
    const float* __restrict__ x, const float* __restrict__ g,
    const float* __restrict__ bt, float* __restrict__ y)
{
    int row = blockIdx.x;
    int t = threadIdx.x;
    float4 v = *(const float4*)&x[(size_t)row * 1024 + t * 4];
    float mean, rstd;
    block_stats(v, t, mean, rstd);
    float4 gv = *(const float4*)&g[t * 4];
    float4 bv = *(const float4*)&bt[t * 4];
    float ln[4] = {
        (v.x - mean) * rstd * gv.x + bv.x,
        (v.y - mean) * rstd * gv.y + bv.y,
        (v.z - mean) * rstd * gv.z + bv.z,
        (v.w - mean) * rstd * gv.w + bv.w
    };
    float bcol = (float)(row & 1);
    float o4[4];
    #pragma unroll
    for (int j = 0; j < 4; j++) {
        int d = t * 4 + j;
        float e = (float)(d & ~1) * (1.f / 1024.f);
        float freq = __expf(-9.210340371976184f * e);
        float ang = bcol * freq;
        float pe = (d & 1) ? cosf(ang) : sinf(ang);
        o4[j] = 2.f * ln[j] + pe;
    }
    float4 o; o.x = o4[0]; o.y = o4[1]; o.z = o4[2]; o.w = o4[3];
    *(float4*)&y[(size_t)row * 1024 + t * 4] = o;
}

// ================= launch ==================================================
extern "C" void kernel_launch(void* const* d_in, const int* in_sizes, int n_in,
                              void* d_out, int out_size)
{
    const float* dec = (const float*)d_in[0];
    const float* Wq  = (const float*)d_in[1];
    const float* Wkv = (const float*)d_in[2];
    const float* Wo  = (const float*)d_in[3];
    const float* g1  = (const float*)d_in[4];
    const float* b1  = (const float*)d_in[5];
    const float* Wff = (const float*)d_in[6];
    const float* g2  = (const float*)d_in[7];
    const float* b2  = (const float*)d_in[8];
    float* out = (float*)d_out;

    __nv_bfloat16 *dh, *dl, *wqh, *wql, *wkvh, *wkvl, *woh, *wol, *wffh, *wffl;
    __nv_bfloat16 *qh, *ql, *kh, *kl, *vth, *vtl, *vech, *vecl, *h1h, *h1l;
    float *h0, *f0;
    cudaGetSymbolAddress((void**)&dh, g_dh);     cudaGetSymbolAddress((void**)&dl, g_dl);
    cudaGetSymbolAddress((void**)&wqh, g_wqh);   cudaGetSymbolAddress((void**)&wql, g_wql);
    cudaGetSymbolAddress((void**)&wkvh, g_wkvh); cudaGetSymbolAddress((void**)&wkvl, g_wkvl);
    cudaGetSymbolAddress((void**)&woh, g_woh);   cudaGetSymbolAddress((void**)&wol, g_wol);
    cudaGetSymbolAddress((void**)&wffh, g_wffh); cudaGetSymbolAddress((void**)&wffl, g_wffl);
    cudaGetSymbolAddress((void**)&qh, g_qh);     cudaGetSymbolAddress((void**)&ql, g_ql);
    cudaGetSymbolAddress((void**)&kh, g_kh);     cudaGetSymbolAddress((void**)&kl, g_kl);
    cudaGetSymbolAddress((void**)&vth, g_vth);   cudaGetSymbolAddress((void**)&vtl, g_vtl);
    cudaGetSymbolAddress((void**)&vech, g_vech); cudaGetSymbolAddress((void**)&vecl, g_vecl);
    cudaGetSymbolAddress((void**)&h1h, g_h1h);   cudaGetSymbolAddress((void**)&h1l, g_h1l);
    cudaGetSymbolAddress((void**)&h0, g_h0);     cudaGetSymbolAddress((void**)&f0, g_f0);

    cudaFuncSetAttribute(gemm_bf16<0>, cudaFuncAttributeMaxDynamicSharedMemorySize, GSMEM_BYTES);
    cudaFuncSetAttribute(gemm_bf16<1>, cudaFuncAttributeMaxDynamicSharedMemorySize, GSMEM_BYTES);
    cudaFuncSetAttribute(gemm_bf16<2>, cudaFuncAttributeMaxDynamicSharedMemorySize, GSMEM_BYTES);
    cudaFuncSetAttribute(gemm_bf16<3>, cudaFuncAttributeMaxDynamicSharedMemorySize, GSMEM_BYTES);
    cudaFuncSetAttribute(attn_tc, cudaFuncAttributeMaxDynamicSharedMemorySize, ASMEM_BYTES);

    // conversions
    conv_split<<<(MTOK*DM/4 + 255)/256, 256>>>(dec, dh, dl, MTOK*DM/4);
    conv_split<<<(DM*DM/4 + 255)/256, 256>>>(Wq, wqh, wql, DM*DM/4);
    conv_split<<<(2*DM*DM/4 + 255)/256, 256>>>(Wkv, wkvh, wkvl, 2*DM*DM/4);
    conv_split<<<(DM*DM/4 + 255)/256, 256>>>(Wo, woh, wol, DM*DM/4);
    conv_split<<<(DM*DM/4 + 255)/256, 256>>>(Wff, wffh, wffl, DM*DM/4);

    // q = dec @ Wq^T -> planes
    gemm_bf16<2><<<dim3(8, 32), 256, GSMEM_BYTES>>>(
        dh, dl, wqh, wql, nullptr, nullptr, nullptr,
        nullptr, qh, ql, nullptr, nullptr, MTOK, 1024, 1024);
    // kv = dec @ Wkv^T -> K planes + V^T planes
    gemm_bf16<3><<<dim3(16, 32), 256, GSMEM_BYTES>>>(
        dh, dl, wkvh, wkvl, nullptr, nullptr, nullptr,
        nullptr, kh, kl, vth, vtl, MTOK, 2048, 1024);
    // attention -> vec planes
    attn_tc<<<dim3(SEQ/128, BATCH, NH), 256, ASMEM_BYTES>>>(
        qh, ql, kh, kl, vth, vtl, vech, vecl);
    // h0 = dec + vec @ Wo^T  (fp32)
    gemm_bf16<0><<<dim3(8, 32), 256, GSMEM_BYTES>>>(
        vech, vecl, woh, wol, dec, nullptr, nullptr,
        h0, nullptr, nullptr, nullptr, nullptr, MTOK, 1024, 1024);
    // h1 = LN(h0) -> planes
    ln_kernel<<<MTOK, 256>>>(h0, g1, b1, h1h, h1l);
    // f0 = h1 + h1 @ Wff^T (fp32, Add reconstructed from planes)
    gemm_bf16<1><<<dim3(8, 32), 256, GSMEM_BYTES>>>(
        h1h, h1l, wffh, wffl, nullptr, h1h, h1l,
        f0, nullptr, nullptr, nullptr, nullptr, MTOK, 1024, 1024);
    // out = 2*LN(f0) + pe[b]
    ln_final_kernel<<<MTOK, 256>>>(f0, g2, b2, out);
}

// round 6
// speedup vs baseline: 2.6870x; 1.0450x over previous
#include <cuda_runtime.h>
#include <cuda_bf16.h>
#include <cstdint>

// Problem constants
#define SEQ   2048
#define BATCH 2
#define DM    1024
#define NH    16
#define DH    64
#define MTOK  (SEQ*BATCH)   // 4096 token rows

// ---------------- scratch (device globals) --------------------------------
__device__ __nv_bfloat16 g_dh [MTOK * DM],      g_dl [MTOK * DM];
__device__ __nv_bfloat16 g_wqh[DM * DM],        g_wql[DM * DM];
__device__ __nv_bfloat16 g_wkvh[2 * DM * DM],   g_wkvl[2 * DM * DM];
__device__ __nv_bfloat16 g_woh[DM * DM],        g_wol[DM * DM];
__device__ __nv_bfloat16 g_wffh[DM * DM],       g_wffl[DM * DM];
__device__ __nv_bfloat16 g_qh [MTOK * DM],      g_ql [MTOK * DM];
__device__ __nv_bfloat16 g_kh [MTOK * DM],      g_kl [MTOK * DM];
__device__ __nv_bfloat16 g_vth[BATCH*NH*DH*SEQ], g_vtl[BATCH*NH*DH*SEQ]; // [b,n][d][j]
__device__ __nv_bfloat16 g_vech[MTOK * DM],     g_vecl[MTOK * DM];
__device__ __nv_bfloat16 g_h1h[MTOK * DM],      g_h1l[MTOK * DM];
__device__ float g_h0[MTOK * DM];
__device__ float g_f0[MTOK * DM];

// ===================== common helpers ======================================
__device__ __forceinline__ void ldsm_x4(uint32_t r[4], uint32_t addr) {
    asm volatile("ldmatrix.sync.aligned.m8n8.x4.shared.b16 {%0,%1,%2,%3}, [%4];\n"
                 : "=r"(r[0]), "=r"(r[1]), "=r"(r[2]), "=r"(r[3]) : "r"(addr));
}

__device__ __forceinline__ void mma16816(float c[4],
                                         uint32_t a0, uint32_t a1, uint32_t a2, uint32_t a3,
                                         uint32_t b0, uint32_t b1) {
    asm volatile(
        "mma.sync.aligned.m16n8k16.row.col.f32.bf16.bf16.f32 "
        "{%0,%1,%2,%3}, {%4,%5,%6,%7}, {%8,%9}, {%0,%1,%2,%3};\n"
        : "+f"(c[0]), "+f"(c[1]), "+f"(c[2]), "+f"(c[3])
        : "r"(a0), "r"(a1), "r"(a2), "r"(a3), "r"(b0), "r"(b1));
}

__device__ __forceinline__ void cp16(uint32_t dst, const void* src) {
    asm volatile("cp.async.cg.shared.global [%0], [%1], 16;\n" :: "r"(dst), "l"(src));
}
#define CP_COMMIT()  asm volatile("cp.async.commit_group;\n")
#define CP_WAIT(n)   asm volatile("cp.async.wait_group %0;\n" :: "n"(n))

__device__ __forceinline__ void split4(float4 v, uint32_t hp[2], uint32_t lp[2]) {
    uint32_t u0 = __float_as_uint(v.x), u1 = __float_as_uint(v.y);
    uint32_t u2 = __float_as_uint(v.z), u3 = __float_as_uint(v.w);
    hp[0] = __byte_perm(u0, u1, 0x7632);
    hp[1] = __byte_perm(u2, u3, 0x7632);
    float r0 = v.x - __uint_as_float(u0 & 0xffff0000u);
    float r1 = v.y - __uint_as_float(u1 & 0xffff0000u);
    float r2 = v.z - __uint_as_float(u2 & 0xffff0000u);
    float r3 = v.w - __uint_as_float(u3 & 0xffff0000u);
    __nv_bfloat162 l01 = __floats2bfloat162_rn(r0, r1);
    __nv_bfloat162 l23 = __floats2bfloat162_rn(r2, r3);
    lp[0] = *(uint32_t*)&l01;
    lp[1] = *(uint32_t*)&l23;
}

__device__ __forceinline__ uint32_t pack_hi2(float a, float b) {
    return __byte_perm(__float_as_uint(a), __float_as_uint(b), 0x7632);
}
__device__ __forceinline__ uint32_t pack_lo2(float a, float b) {
    float ra = a - __uint_as_float(__float_as_uint(a) & 0xffff0000u);
    float rb = b - __uint_as_float(__float_as_uint(b) & 0xffff0000u);
    __nv_bfloat162 l = __floats2bfloat162_rn(ra, rb);
    return *(uint32_t*)&l;
}
__device__ __forceinline__ unsigned short hi16(float x) {
    return (unsigned short)(__float_as_uint(x) >> 16);
}
__device__ __forceinline__ unsigned short lo16(float x) {
    float r = x - __uint_as_float(__float_as_uint(x) & 0xffff0000u);
    __nv_bfloat16 b = __float2bfloat16_rn(r);
    return *(unsigned short*)&b;
}

// ================= fp32 -> hi/lo plane conversion =========================
__global__ void __launch_bounds__(256) conv_split(
    const float* __restrict__ x, __nv_bfloat16* __restrict__ h,
    __nv_bfloat16* __restrict__ l, int n4)
{
    int i = blockIdx.x * 256 + threadIdx.x;
    if (i >= n4) return;
    float4 v = ((const float4*)x)[i];
    uint32_t hp[2], lp[2];
    split4(v, hp, lp);
    ((uint2*)h)[i] = make_uint2(hp[0], hp[1]);
    ((uint2*)l)[i] = make_uint2(lp[0], lp[1]);
}

// ===================== bf16-plane GEMM (split-3x, cp.async) ================
#define GP_STRIDE 40
#define GP_BYTES  10240
#define GSTAGE_BYTES (4 * GP_BYTES)
#define GSMEM_BYTES (2 * GSTAGE_BYTES)   // 81920

template<int MODE>
__global__ void __launch_bounds__(256, 2) gemm_bf16(
    const __nv_bfloat16* __restrict__ Ah, const __nv_bfloat16* __restrict__ Al,
    const __nv_bfloat16* __restrict__ Bh, const __nv_bfloat16* __restrict__ Bl,
    const float* __restrict__ AddF,
    const __nv_bfloat16* __restrict__ AddH, const __nv_bfloat16* __restrict__ AddL,
    float* __restrict__ Cf,
    __nv_bfloat16* __restrict__ Ch, __nv_bfloat16* __restrict__ Cl,
    __nv_bfloat16* __restrict__ Vth, __nv_bfloat16* __restrict__ Vtl,
    int M, int N, int K)
{
    extern __shared__ __align__(16) unsigned char smraw[];
    uint32_t sbase = (uint32_t)__cvta_generic_to_shared(smraw);

    const int tid  = threadIdx.x;
    const int lane = tid & 31;
    const int wid  = tid >> 5;
    const int wm   = wid >> 2;
    const int wn   = wid & 3;
    const int bm   = blockIdx.y * 128;
    const int bn   = blockIdx.x * 128;

    const int plane = tid >> 6;
    const __nv_bfloat16* srcbase =
        (plane == 0) ? Ah + (size_t)bm * K :
        (plane == 1) ? Al + (size_t)bm * K :
        (plane == 2) ? Bh + (size_t)bn * K :
                       Bl + (size_t)bn * K;

    auto issue = [&](int k0, int buf) {
        uint32_t dbase = sbase + buf * GSTAGE_BYTES + plane * GP_BYTES;
        #pragma unroll
        for (int i = 0; i < 8; i++) {
            int chunk = (tid & 63) + 64 * i;
            int row = chunk >> 2, c = chunk & 3;
            cp16(dbase + row * 80 + c * 16,
                 srcbase + (size_t)row * K + k0 + c * 8);
        }
        CP_COMMIT();
    };

    float acc[4][4][4] = {};

    const uint32_t arow = lane & 15;
    const uint32_t acol = ((lane >> 4) & 1) * 8;
    const uint32_t brow = (lane & 7) + ((lane >> 4) & 1) * 8;
    const uint32_t bcol = ((lane >> 3) & 1) * 8;

    auto compute = [&](int buf) {
        uint32_t base = sbase + buf * GSTAGE_BYTES;
        #pragma unroll
        for (int s = 0; s < 2; s++) {
            uint32_t ah[4][4], al[4][4], bh[2][4], bl[2][4];
            #pragma unroll
            for (int mt = 0; mt < 4; mt++) {
                uint32_t off = (((wm * 64 + mt * 16 + arow) * GP_STRIDE) + acol + s * 16) << 1;
                ldsm_x4(ah[mt], base + off);
                ldsm_x4(al[mt], base + GP_BYTES + off);
            }
            #pragma unroll
            for (int np = 0; np < 2; np++) {
                uint32_t off = (((wn * 32 + np * 16 + brow) * GP_STRIDE) + bcol + s * 16) << 1;
                ldsm_x4(bh[np], base + 2 * GP_BYTES + off);
                ldsm_x4(bl[np], base + 3 * GP_BYTES + off);
            }
            #pragma unroll
            for (int mt = 0; mt < 4; mt++)
                #pragma unroll
                for (int nt = 0; nt < 4; nt++) {
                    int p = nt >> 1, q = (nt & 1) * 2;
                    mma16816(acc[mt][nt], ah[mt][0], ah[mt][1], ah[mt][2], ah[mt][3],
                             bh[p][q], bh[p][q + 1]);
                    mma16816(acc[mt][nt], ah[mt][0], ah[mt][1], ah[mt][2], ah[mt][3],
                             bl[p][q], bl[p][q + 1]);
                    mma16816(acc[mt][nt], al[mt][0], al[mt][1], al[mt][2], al[mt][3],
                             bh[p][q], bh[p][q + 1]);
                }
        }
    };

    issue(0, 0);
    issue(32, 1);
    CP_WAIT(1);
    __syncthreads();

    for (int k0 = 0; k0 < K; k0 += 32) {
        int buf = (k0 >> 5) & 1;
        compute(buf);
        __syncthreads();
        if (k0 + 64 < K) issue(k0 + 64, buf);
        if (k0 + 32 < K) { CP_WAIT(1); __syncthreads(); }
    }

    #pragma unroll
    for (int mt = 0; mt < 4; mt++) {
        #pragma unroll
        for (int nt = 0; nt < 4; nt++) {
            int r0 = bm + wm * 64 + mt * 16 + (lane >> 2);
            int c  = bn + wn * 32 + nt * 8 + (lane & 3) * 2;
            float a0 = acc[mt][nt][0], a1 = acc[mt][nt][1];
            float a2 = acc[mt][nt][2], a3 = acc[mt][nt][3];
            if constexpr (MODE == 0) {
                size_t o0 = (size_t)r0 * N + c, o1 = (size_t)(r0 + 8) * N + c;
                float2 x0 = *(const float2*)&AddF[o0];
                float2 x1 = *(const float2*)&AddF[o1];
                *(float2*)&Cf[o0] = make_float2(a0 + x0.x, a1 + x0.y);
                *(float2*)&Cf[o1] = make_float2(a2 + x1.x, a3 + x1.y);
            } else if constexpr (MODE == 1) {
                size_t o0 = (size_t)r0 * N + c, o1 = (size_t)(r0 + 8) * N + c;
                __nv_bfloat162 h0v = *(const __nv_bfloat162*)&AddH[o0];
                __nv_bfloat162 l0v = *(const __nv_bfloat162*)&AddL[o0];
                __nv_bfloat162 h1v = *(const __nv_bfloat162*)&AddH[o1];
                __nv_bfloat162 l1v = *(const __nv_bfloat162*)&AddL[o1];
                a0 += __bfloat162float(h0v.x) + __bfloat162float(l0v.x);
                a1 += __bfloat162float(h0v.y) + __bfloat162float(l0v.y);
                a2 += __bfloat162float(h1v.x) + __bfloat162float(l1v.x);
                a3 += __bfloat162float(h1v.y) + __bfloat162float(l1v.y);
                *(float2*)&Cf[o0] = make_float2(a0, a1);
                *(float2*)&Cf[o1] = make_float2(a2, a3);
            } else if constexpr (MODE == 2) {
                size_t o0 = (size_t)r0 * N + c, o1 = (size_t)(r0 + 8) * N + c;
                ((uint32_t*)Ch)[o0 >> 1] = pack_hi2(a0, a1);
                ((uint32_t*)Cl)[o0 >> 1] = pack_lo2(a0, a1);
                ((uint32_t*)Ch)[o1 >> 1] = pack_hi2(a2, a3);
                ((uint32_t*)Cl)[o1 >> 1] = pack_lo2(a2, a3);
            } else {
                if (c < 1024) {
                    size_t o0 = (size_t)r0 * 1024 + c, o1 = (size_t)(r0 + 8) * 1024 + c;
                    ((uint32_t*)Ch)[o0 >> 1] = pack_hi2(a0, a1);
                    ((uint32_t*)Cl)[o0 >> 1] = pack_lo2(a0, a1);
                    ((uint32_t*)Ch)[o1 >> 1] = pack_hi2(a2, a3);
                    ((uint32_t*)Cl)[o1 >> 1] = pack_lo2(a2, a3);
                } else {
                    int e = c - 1024, nn = e >> 6, dd = e & 63;
                    int b0 = r0 & 1, j0 = r0 >> 1;
                    size_t base = ((size_t)(b0 * 16 + nn) * 64 + dd) * 2048;
                    unsigned short* VH = (unsigned short*)Vth;
                    unsigned short* VL = (unsigned short*)Vtl;
                    VH[base + j0]            = hi16(a0);
                    VH[base + 2048 + j0]     = hi16(a1);
                    VH[base + j0 + 4]        = hi16(a2);
                    VH[base + 2048 + j0 + 4] = hi16(a3);
                    VL[base + j0]            = lo16(a0);
                    VL[base + 2048 + j0]     = lo16(a1);
                    VL[base + j0 + 4]        = lo16(a2);
                    VL[base + 2048 + j0 + 4] = lo16(a3);
                }
            }
        }
    }
}

// ================= Tensor-core flash attention (512 thr, 256 q-rows) ======
// 16 warps, warp = 16 q-rows. Q hi/lo [256][72] persistent in smem+regs;
// KV double-buffered stages (Kh|Kl|Vh|Vl)[64][72]. V pre-transposed.
#define AP 72
#define QPLANE2 (256 * AP)              // 18432 elems
#define KPLANE (64 * AP)                // 4608
#define ASTAGE (4 * KPLANE)             // 18432
#define ASMEM_BYTES ((2 * QPLANE2 + 2 * ASTAGE) * 2)   // 147456

__global__ void __launch_bounds__(512) attn_tc(
    const __nv_bfloat16* __restrict__ qh, const __nv_bfloat16* __restrict__ ql,
    const __nv_bfloat16* __restrict__ kh, const __nv_bfloat16* __restrict__ kl,
    const __nv_bfloat16* __restrict__ vth, const __nv_bfloat16* __restrict__ vtl,
    __nv_bfloat16* __restrict__ vech, __nv_bfloat16* __restrict__ vecl)
{
    extern __shared__ __align__(16) unsigned char smraw[];
    uint32_t sbase = (uint32_t)__cvta_generic_to_shared(smraw);

    const int tid  = threadIdx.x;
    const int lane = tid & 31;
    const int wid  = tid >> 5;                 // 0..15
    const int i0   = blockIdx.x * 256;
    const int b    = blockIdx.y;
    const int n    = blockIdx.z;

    // ---- Q staging: 2 planes x 256 rows x 8 chunks of 16B ----
    {
        int qp = tid >> 8;                     // 0..1 (256 threads per plane)
        const __nv_bfloat16* src0 = (qp ? ql : qh) + (size_t)b * 1024 + n * 64;
        uint32_t dbase = sbase + qp * QPLANE2 * 2;
        #pragma unroll
        for (int i = 0; i < 8; i++) {
            int chunk = (tid & 255) + 256 * i; // 0..2047
            int row = chunk >> 3, c = chunk & 7;
            cp16(dbase + row * 144 + c * 16,
                 src0 + (size_t)(i0 + row) * 2048 + c * 8);
        }
    }

    // ---- KV staging: 4 planes x 512 chunks, 128 threads per plane ----
    const int plane = tid >> 7;                // 0..3
    const __nv_bfloat16* kvsrc =
        (plane == 0) ? kh + (size_t)b * 1024 + n * 64 :
        (plane == 1) ? kl + (size_t)b * 1024 + n * 64 :
        (plane == 2) ? vth + (size_t)(b * 16 + n) * 64 * 2048 :
                       vtl + (size_t)(b * 16 + n) * 64 * 2048;
    const bool isK = (plane < 2);

    auto issue_kv = [&](int j0, int buf) {
        uint32_t dbase = sbase + (2 * QPLANE2 + buf * ASTAGE + plane * KPLANE) * 2;
        #pragma unroll
        for (int i = 0; i < 4; i++) {
            int chunk = (tid & 127) + 128 * i; // 0..511
            int row = chunk >> 3, c = chunk & 7;
            const __nv_bfloat16* s = isK
                ? kvsrc + (size_t)(j0 + row) * 2048 + c * 8
                : kvsrc + (size_t)row * 2048 + j0 + c * 8;
            cp16(dbase + row * 144 + c * 16, s);
        }
        CP_COMMIT();
    };

    issue_kv(0, 0);     // group 0 includes Q + stage0
    issue_kv(64, 1);
    CP_WAIT(1);
    __syncthreads();

    // ---- Q fragments persistent in registers ----
    const uint32_t arow = lane & 15;
    const uint32_t acol = (lane >> 4) * 8;
    uint32_t qfh[4][4], qfl[4][4];
    #pragma unroll
    for (int kc = 0; kc < 4; kc++) {
        uint32_t off = ((wid * 16 + arow) * AP + kc * 16 + acol) * 2;
        ldsm_x4(qfh[kc], sbase + off);
        ldsm_x4(qfl[kc], sbase + QPLANE2 * 2 + off);
    }

    const uint32_t brow = (lane & 7) + ((lane >> 4) & 1) * 8;
    const uint32_t bcol = ((lane >> 3) & 1) * 8;

    float acc_o[8][4] = {};
    float m0 = -1e30f, m1 = -1e30f, l0 = 0.f, l1 = 0.f;
    const float SC = 0.125f;

    for (int j0 = 0; j0 < SEQ; j0 += 64) {
        int buf = (j0 >> 6) & 1;
        uint32_t stg = sbase + (2 * QPLANE2 + buf * ASTAGE) * 2;

        // ---- S = Q K^T (split 3x) ----
        float s_acc[8][4] = {};
        #pragma unroll
        for (int kc = 0; kc < 4; kc++) {
            uint32_t bh[4][4], blr[4][4];
            #pragma unroll
            for (int np = 0; np < 4; np++) {
                uint32_t off = ((np * 16 + brow) * AP + kc * 16 + bcol) * 2;
                ldsm_x4(bh[np],  stg + off);
                ldsm_x4(blr[np], stg + KPLANE * 2 + off);
            }
            #pragma unroll
            for (int nt = 0; nt < 8; nt++) {
                int p = nt >> 1, qd = (nt & 1) * 2;
                mma16816(s_acc[nt], qfh[kc][0], qfh[kc][1], qfh[kc][2], qfh[kc][3],
                         bh[p][qd], bh[p][qd + 1]);
                mma16816(s_acc[nt], qfh[kc][0], qfh[kc][1], qfh[kc][2], qfh[kc][3],
                         blr[p][qd], blr[p][qd + 1]);
                mma16816(s_acc[nt], qfl[kc][0], qfl[kc][1], qfl[kc][2], qfl[kc][3],
                         bh[p][qd], bh[p][qd + 1]);
            }
        }

        // ---- online softmax ----
        float vx0 = -1e30f, vx1 = -1e30f;
        #pragma unroll
        for (int nt = 0; nt < 8; nt++) {
            vx0 = fmaxf(vx0, fmaxf(s_acc[nt][0], s_acc[nt][1]));
            vx1 = fmaxf(vx1, fmaxf(s_acc[nt][2], s_acc[nt][3]));
        }
        vx0 *= SC; vx1 *= SC;
        #pragma unroll
        for (int off = 1; off <= 2; off <<= 1) {
            vx0 = fmaxf(vx0, __shfl_xor_sync(0xffffffffu, vx0, off));
            vx1 = fmaxf(vx1, __shfl_xor_sync(0xffffffffu, vx1, off));
        }
        float mn0 = fmaxf(m0, vx0), mn1 = fmaxf(m1, vx1);
        float al0 = __expf(m0 - mn0), al1 = __expf(m1 - mn1);
        float ls0 = 0.f, ls1 = 0.f;
        #pragma unroll
        for (int nt = 0; nt < 8; nt++) {
            float p0 = __expf(s_acc[nt][0] * SC - mn0);
            float p1 = __expf(s_acc[nt][1] * SC - mn0);
            float p2 = __expf(s_acc[nt][2] * SC - mn1);
            float p3 = __expf(s_acc[nt][3] * SC - mn1);
            ls0 += p0 + p1; ls1 += p2 + p3;
            s_acc[nt][0] = p0; s_acc[nt][1] = p1;
            s_acc[nt][2] = p2; s_acc[nt][3] = p3;
        }
        #pragma unroll
        for (int off = 1; off <= 2; off <<= 1) {
            ls0 += __shfl_xor_sync(0xffffffffu, ls0, off);
            ls1 += __shfl_xor_sync(0xffffffffu, ls1, off);
        }
        l0 = l0 * al0 + ls0; l1 = l1 * al1 + ls1;
        m0 = mn0; m1 = mn1;
        #pragma unroll
        for (int nt = 0; nt < 8; nt++) {
            acc_o[nt][0] *= al0; acc_o[nt][1] *= al0;
            acc_o[nt][2] *= al1; acc_o[nt][3] *= al1;
        }

        // ---- pack P fragments ----
        uint32_t pah[4][4], pal[4][4];
        #pragma unroll
        for (int kc = 0; kc < 4; kc++) {
            pah[kc][0] = pack_hi2(s_acc[2*kc][0],   s_acc[2*kc][1]);
            pah[kc][1] = pack_hi2(s_acc[2*kc][2],   s_acc[2*kc][3]);
            pah[kc][2] = pack_hi2(s_acc[2*kc+1][0], s_acc[2*kc+1][1]);
            pah[kc][3] = pack_hi2(s_acc[2*kc+1][2], s_acc[2*kc+1][3]);
            pal[kc][0] = pack_lo2(s_acc[2*kc][0],   s_acc[2*kc][1]);
            pal[kc][1] = pack_lo2(s_acc[2*kc][2],   s_acc[2*kc][3]);
            pal[kc][2] = pack_lo2(s_acc[2*kc+1][0], s_acc[2*kc+1][1]);
            pal[kc][3] = pack_lo2(s_acc[2*kc+1][2], s_acc[2*kc+1][3]);
        }

        // ---- O += P V (split 3x) ----
        #pragma unroll
        for (int kc = 0; kc < 4; kc++) {
            uint32_t vh[4][4], vl[4][4];
            #pragma unroll
            for (int np = 0; np < 4; np++) {
                uint32_t off = ((np * 16 + brow) * AP + kc * 16 + bcol) * 2;
                ldsm_x4(vh[np], stg + 2 * KPLANE * 2 + off);
                ldsm_x4(vl[np], stg + 3 * KPLANE * 2 + off);
            }
            #pragma unroll
            for (int nt = 0; nt < 8; nt++) {
                int p = nt >> 1, qd = (nt & 1) * 2;
                mma16816(acc_o[nt], pah[kc][0], pah[kc][1], pah[kc][2], pah[kc][3],
                         vh[p][qd], vh[p][qd + 1]);
                mma16816(acc_o[nt], pah[kc][0], pah[kc][1], pah[kc][2], pah[kc][3],
                         vl[p][qd], vl[p][qd + 1]);
                mma16816(acc_o[nt], pal[kc][0], pal[kc][1], pal[kc][2], pal[kc][3],
                         vh[p][qd], vh[p][qd + 1]);
            }
        }

        __syncthreads();
        if (j0 + 128 < SEQ) issue_kv(j0 + 128, buf);
        if (j0 + 64 < SEQ) { CP_WAIT(1); __syncthreads(); }
    }

    // ---- epilogue ----
    float inv0 = 1.f / l0, inv1 = 1.f / l1;
    int row0 = i0 + wid * 16 + (lane >> 2);
    int colb = n * 64 + (lane & 3) * 2;
    #pragma unroll
    for (int nt = 0; nt < 8; nt++) {
        float a0 = acc_o[nt][0] * inv0, a1 = acc_o[nt][1] * inv0;
        float a2 = acc_o[nt][2] * inv1, a3 = acc_o[nt][3] * inv1;
        size_t o0 = ((size_t)row0 * 2 + b) * 1024 + colb + nt * 8;
        size_t o1 = ((size_t)(row0 + 8) * 2 + b) * 1024 + colb + nt * 8;
        ((uint32_t*)vech)[o0 >> 1] = pack_hi2(a0, a1);
        ((uint32_t*)vecl)[o0 >> 1] = pack_lo2(a0, a1);
        ((uint32_t*)vech)[o1 >> 1] = pack_hi2(a2, a3);
        ((uint32_t*)vecl)[o1 >> 1] = pack_lo2(a2, a3);
    }
}

// ================= LayerNorm kernels ======================================
__device__ __forceinline__ void block_stats(float4 v, int t, float& mean, float& rstd)
{
    __shared__ float as[8], aq[8];
    float s  = v.x + v.y + v.z + v.w;
    float ss = v.x*v.x + v.y*v.y + v.z*v.z + v.w*v.w;
    #pragma unroll
    for (int off = 16; off; off >>= 1) {
        s  += __shfl_xor_sync(0xffffffffu, s, off);
        ss += __shfl_xor_sync(0xffffffffu, ss, off);
    }
    if ((t & 31) == 0) { as[t >> 5] = s; aq[t >> 5] = ss; }
    __syncthreads();
    s = 0.f; ss = 0.f;
    #pragma unroll
    for (int w = 0; w < 8; w++) { s += as[w]; ss += aq[w]; }
    mean = s * (1.f / 1024.f);
    float var = ss * (1.f / 1024.f) - mean * mean;
    rstd = rsqrtf(var + 1e-5f);
}

__global__ void __launch_bounds__(256) ln_kernel(
    const float* __restrict__ x, const float* __restrict__ g,
    const float* __restrict__ bt, __nv_bfloat16* __restrict__ yh,
    __nv_bfloat16* __restrict__ yl)
{
    int row = blockIdx.x;
    int t = threadIdx.x;
    float4 v = *(const float4*)&x[(size_t)row * 1024 + t * 4];
    float mean, rstd;
    block_stats(v, t, mean, rstd);
    float4 gv = *(const float4*)&g[t * 4];
    float4 bv = *(const float4*)&bt[t * 4];
    float o0 = (v.x - mean) * rstd * gv.x + bv.x;
    float o1 = (v.y - mean) * rstd * gv.y + bv.y;
    float o2 = (v.z - mean) * rstd * gv.z + bv.z;
    float o3 = (v.w - mean) * rstd * gv.w + bv.w;
    size_t idx = ((size_t)row * 1024 + t * 4) >> 1;
    ((uint2*)yh)[idx >> 1] = make_uint2(pack_hi2(o0, o1), pack_hi2(o2, o3));
    ((uint2*)yl)[idx >> 1] = make_uint2(pack_lo2(o0, o1), pack_lo2(o2, o3));
}

__global__ void __launch_bounds__(256) ln_final_kernel(
    const float* __restrict__ x, const float* __restrict__ g,
    const float* __restrict__ bt, float* __restrict__ y)
{
    int row = blockIdx.x;
    int t = threadIdx.x;
    float4 v = *(const float4*)&x[(size_t)row * 1024 + t * 4];
    float mean, rstd;
    block_stats(v, t, mean, rstd);
    float4 gv = *(const float4*)&g[t * 4];
    float4 bv = *(const float4*)&bt[t * 4];
    float ln[4] = {
        (v.x - mean) * rstd * gv.x + bv.x,
        (v.y - mean) * rstd * gv.y + bv.y,
        (v.z - mean) * rstd * gv.z + bv.z,
        (v.w - mean) * rstd * gv.w + bv.w
    };
    float bcol = (float)(row & 1);
    float o4[4];
    #pragma unroll
    for (int j = 0; j < 4; j++) {
        int d = t * 4 + j;
        float e = (float)(d & ~1) * (1.f / 1024.f);
        float freq = __expf(-9.210340371976184f * e);
        float ang = bcol * freq;
        float pe = (d & 1) ? cosf(ang) : sinf(ang);
        o4[j] = 2.f * ln[j] + pe;
    }
    float4 o; o.x = o4[0]; o.y = o4[1]; o.z = o4[2]; o.w = o4[3];
    *(float4*)&y[(size_t)row * 1024 + t * 4] = o;
}

// ================= launch ==================================================
extern "C" void kernel_launch(void* const* d_in, const int* in_sizes, int n_in,
                              void* d_out, int out_size)
{
    const float* dec = (const float*)d_in[0];
    const float* Wq  = (const float*)d_in[1];
    const float* Wkv = (const float*)d_in[2];
    const float* Wo  = (const float*)d_in[3];
    const float* g1  = (const float*)d_in[4];
    const float* b1  = (const float*)d_in[5];
    const float* Wff = (const float*)d_in[6];
    const float* g2  = (const float*)d_in[7];
    const float* b2  = (const float*)d_in[8];
    float* out = (float*)d_out;

    __nv_bfloat16 *dh, *dl, *wqh, *wql, *wkvh, *wkvl, *woh, *wol, *wffh, *wffl;
    __nv_bfloat16 *qh, *ql, *kh, *kl, *vth, *vtl, *vech, *vecl, *h1h, *h1l;
    float *h0, *f0;
    cudaGetSymbolAddress((void**)&dh, g_dh);     cudaGetSymbolAddress((void**)&dl, g_dl);
    cudaGetSymbolAddress((void**)&wqh, g_wqh);   cudaGetSymbolAddress((void**)&wql, g_wql);
    cudaGetSymbolAddress((void**)&wkvh, g_wkvh); cudaGetSymbolAddress((void**)&wkvl, g_wkvl);
    cudaGetSymbolAddress((void**)&woh, g_woh);   cudaGetSymbolAddress((void**)&wol, g_wol);
    cudaGetSymbolAddress((void**)&wffh, g_wffh); cudaGetSymbolAddress((void**)&wffl, g_wffl);
    cudaGetSymbolAddress((void**)&qh, g_qh);     cudaGetSymbolAddress((void**)&ql, g_ql);
    cudaGetSymbolAddress((void**)&kh, g_kh);     cudaGetSymbolAddress((void**)&kl, g_kl);
    cudaGetSymbolAddress((void**)&vth, g_vth);   cudaGetSymbolAddress((void**)&vtl, g_vtl);
    cudaGetSymbolAddress((void**)&vech, g_vech); cudaGetSymbolAddress((void**)&vecl, g_vecl);
    cudaGetSymbolAddress((void**)&h1h, g_h1h);   cudaGetSymbolAddress((void**)&h1l, g_h1l);
    cudaGetSymbolAddress((void**)&h0, g_h0);     cudaGetSymbolAddress((void**)&f0, g_f0);

    cudaFuncSetAttribute(gemm_bf16<0>, cudaFuncAttributeMaxDynamicSharedMemorySize, GSMEM_BYTES);
    cudaFuncSetAttribute(gemm_bf16<1>, cudaFuncAttributeMaxDynamicSharedMemorySize, GSMEM_BYTES);
    cudaFuncSetAttribute(gemm_bf16<2>, cudaFuncAttributeMaxDynamicSharedMemorySize, GSMEM_BYTES);
    cudaFuncSetAttribute(gemm_bf16<3>, cudaFuncAttributeMaxDynamicSharedMemorySize, GSMEM_BYTES);
    cudaFuncSetAttribute(attn_tc, cudaFuncAttributeMaxDynamicSharedMemorySize, ASMEM_BYTES);

    // conversions
    conv_split<<<(MTOK*DM/4 + 255)/256, 256>>>(dec, dh, dl, MTOK*DM/4);
    conv_split<<<(DM*DM/4 + 255)/256, 256>>>(Wq, wqh, wql, DM*DM/4);
    conv_split<<<(2*DM*DM/4 + 255)/256, 256>>>(Wkv, wkvh, wkvl, 2*DM*DM/4);
    conv_split<<<(DM*DM/4 + 255)/256, 256>>>(Wo, woh, wol, DM*DM/4);
    conv_split<<<(DM*DM/4 + 255)/256, 256>>>(Wff, wffh, wffl, DM*DM/4);

    // q = dec @ Wq^T -> planes
    gemm_bf16<2><<<dim3(8, 32), 256, GSMEM_BYTES>>>(
        dh, dl, wqh, wql, nullptr, nullptr, nullptr,
        nullptr, qh, ql, nullptr, nullptr, MTOK, 1024, 1024);
    // kv = dec @ Wkv^T -> K planes + V^T planes
    gemm_bf16<3><<<dim3(16, 32), 256, GSMEM_BYTES>>>(
        dh, dl, wkvh, wkvl, nullptr, nullptr, nullptr,
        nullptr, kh, kl, vth, vtl, MTOK, 2048, 1024);
    // attention -> vec planes (512 threads, 256 q-rows per CTA)
    attn_tc<<<dim3(SEQ/256, BATCH, NH), 512, ASMEM_BYTES>>>(
        qh, ql, kh, kl, vth, vtl, vech, vecl);
    // h0 = dec + vec @ Wo^T  (fp32)
    gemm_bf16<0><<<dim3(8, 32), 256, GSMEM_BYTES>>>(
        vech, vecl, woh, wol, dec, nullptr, nullptr,
        h0, nullptr, nullptr, nullptr, nullptr, MTOK, 1024, 1024);
    // h1 = LN(h0) -> planes
    ln_kernel<<<MTOK, 256>>>(h0, g1, b1, h1h, h1l);
    // f0 = h1 + h1 @ Wff^T
    gemm_bf16<1><<<dim3(8, 32), 256, GSMEM_BYTES>>>(
        h1h, h1l, wffh, wffl, nullptr, h1h, h1l,
        f0, nullptr, nullptr, nullptr, nullptr, MTOK, 1024, 1024);
    // out = 2*LN(f0) + pe[b]
    ln_final_kernel<<<MTOK, 256>>>(f0, g2, b2, out);
}